// round 2
// baseline (speedup 1.0000x reference)
#include <cuda_runtime.h>

// ct_layer: 5x conv3x3(256->256)+BN on [8,256,96,96], corner pools collapse to
// global row/col maxes (cummax(rev) then cummax(fwd) == broadcast global max).

constexpr int Bn  = 8;
constexpr int Cc  = 256;
constexpr int Hh  = 96;
constexpr int Ww  = 96;
constexpr int TCO = 64;   // couts per block
constexpr int TH  = 8;    // output rows per block
constexpr int TWt = 16;   // output cols per block
constexpr int CIC = 8;    // cin chunk

constexpr int NPOOL = Bn * Cc * Hh;          // 196608 (col/row max buffers)
constexpr int NW    = Cc * Cc * 9;           // 589824 (one conv weight)
constexpr int NTEN  = Bn * Cc * Hh * Ww;     // 18874368

// Scratch: __device__ globals (no allocation allowed in kernel_launch)
__device__ float g_colmax[NPOOL];            // max over h of relu(convbn(x,w_p1))
__device__ float g_rowmax[NPOOL];            // max over w of relu(convbn(x,w_p2))
__device__ float g_c1[NTEN];                 // convbn(x, w_c1) (no act)
__device__ float g_relut[NTEN];              // relu(p_conv + conv1)
__device__ float g_wT[5][NW];                // weights transposed to [ci][k][co]

__global__ void zero_pools_kernel() {
    int i = blockIdx.x * 256 + threadIdx.x;
    if (i < NPOOL) { g_colmax[i] = 0.f; g_rowmax[i] = 0.f; }
}

// OIHW -> [ci][k][co] so smem weight loads are coalesced float4 over co
__global__ void transform_w_kernel(const float* __restrict__ src, int which) {
    int idx = blockIdx.x * 256 + threadIdx.x;
    if (idx < NW) {
        int co = idx & 255;
        int t  = idx >> 8;       // ci*9 + k
        int k  = t % 9;
        int ci = t / 9;
        g_wT[which][idx] = src[(co * Cc + ci) * 9 + k];
    }
}

// EPI: 0 = colmax atomics (p1), 1 = rowmax atomics (p2), 2 = store -> g_c1,
//      3 = pool conv: + g_c1, relu, store -> g_relut (RANK1 input),
//      4 = final: relu, store -> outp (input = g_relut)
template <bool RANK1, int EPI>
__global__ __launch_bounds__(256, 2) void conv3x3_kernel(
    const float* __restrict__ x, int widx,
    const float* __restrict__ gg, const float* __restrict__ bb,
    float* __restrict__ outp)
{
    __shared__ float in_s[CIC][10][18];        // (TH+2) x (TWt+2) halo
    __shared__ float w_s[CIC * 9 * TCO];       // [ci][k][co]

    const float* __restrict__ wT  = g_wT[widx];
    const float* __restrict__ src = (EPI == 4) ? (const float*)g_relut : x;

    const int tid    = threadIdx.x;
    const int lane   = tid & 31;
    const int warp   = tid >> 5;
    const int w0     = blockIdx.x * TWt;
    const int h0     = blockIdx.y * TH;
    const int b      = blockIdx.z >> 2;
    const int cotile = blockIdx.z & 3;
    const int coBase = cotile * TCO + warp * 8;   // this thread's 8 couts
    const int r0     = lane >> 4;                  // 0/1
    const int cwl    = lane & 15;                  // col in tile
    // thread covers rows r0, r0+2, r0+4, r0+6 at col cwl; couts coBase..coBase+7

    float acc[8][4];
    #pragma unroll
    for (int k = 0; k < 8; k++)
        #pragma unroll
        for (int j = 0; j < 4; j++) acc[k][j] = 0.f;

    for (int ci0 = 0; ci0 < Cc; ci0 += CIC) {
        __syncthreads();
        // ---- input tile (10 x 18 halo per ci) ----
        for (int idx = tid; idx < CIC * 10 * 18; idx += 256) {
            int ci  = idx / 180;
            int rem = idx - ci * 180;
            int r   = rem / 18;
            int c2  = rem - r * 18;
            int hg  = h0 - 1 + r;
            int wg  = w0 - 1 + c2;
            float v = 0.f;
            if ((unsigned)hg < 96u && (unsigned)wg < 96u) {
                int cg = b * Cc + ci0 + ci;
                if (RANK1)
                    v = g_colmax[cg * 96 + wg] + g_rowmax[cg * 96 + hg];
                else
                    v = src[(cg * 96 + hg) * 96 + wg];
            }
            in_s[ci][r][c2] = v;
        }
        // ---- weights: CIC*9 rows of 64 floats, coalesced float4 ----
        for (int idx = tid; idx < CIC * 9 * (TCO / 4); idx += 256) {
            int row = idx >> 4;    // ci_l*9 + k
            int c4  = idx & 15;
            const float4* s4 =
                (const float4*)(wT + (ci0 * 9 + row) * Cc + cotile * TCO);
            ((float4*)w_s)[row * 16 + c4] = s4[c4];
        }
        __syncthreads();

        for (int ci = 0; ci < CIC; ci++) {
            #pragma unroll
            for (int kh = 0; kh < 3; kh++) {
                #pragma unroll
                for (int kw = 0; kw < 3; kw++) {
                    float xv[4];
                    #pragma unroll
                    for (int j = 0; j < 4; j++)
                        xv[j] = in_s[ci][r0 + 2 * j + kh][cwl + kw];
                    const float* wp =
                        &w_s[(ci * 9 + kh * 3 + kw) * TCO + warp * 8];
                    float4 wa = *(const float4*)wp;
                    float4 wb = *(const float4*)(wp + 4);
                    float wv[8] = {wa.x, wa.y, wa.z, wa.w,
                                   wb.x, wb.y, wb.z, wb.w};
                    #pragma unroll
                    for (int k = 0; k < 8; k++)
                        #pragma unroll
                        for (int j = 0; j < 4; j++)
                            acc[k][j] = fmaf(wv[k], xv[j], acc[k][j]);
                }
            }
        }
    }

    // ---- epilogue ----
    float gv[8], bv[8];
    #pragma unroll
    for (int k = 0; k < 8; k++) { gv[k] = gg[coBase + k]; bv[k] = bb[coBase + k]; }

    if (EPI == 0) {
        // relu then max over h. Thread: max over its 4 rows (same col),
        // shfl 16 merges the other row-parity, lanes<16 do one atomic per cout.
        #pragma unroll
        for (int k = 0; k < 8; k++) {
            float m = 0.f;
            #pragma unroll
            for (int j = 0; j < 4; j++)
                m = fmaxf(m, acc[k][j] * gv[k] + bv[k]);   // relu folded: m>=0
            m = fmaxf(m, __shfl_xor_sync(0xffffffffu, m, 16));
            if (lane < 16)
                atomicMax(reinterpret_cast<int*>(
                              &g_colmax[(b * Cc + coBase + k) * 96 + w0 + cwl]),
                          __float_as_int(m));
        }
    } else if (EPI == 1) {
        // relu then max over w: butterfly over the 16 cols, lane col==0 atomics
        #pragma unroll
        for (int k = 0; k < 8; k++) {
            #pragma unroll
            for (int j = 0; j < 4; j++) {
                float v = fmaxf(acc[k][j] * gv[k] + bv[k], 0.f);
                v = fmaxf(v, __shfl_xor_sync(0xffffffffu, v, 1));
                v = fmaxf(v, __shfl_xor_sync(0xffffffffu, v, 2));
                v = fmaxf(v, __shfl_xor_sync(0xffffffffu, v, 4));
                v = fmaxf(v, __shfl_xor_sync(0xffffffffu, v, 8));
                if (cwl == 0)
                    atomicMax(reinterpret_cast<int*>(
                                  &g_rowmax[(b * Cc + coBase + k) * 96 +
                                            h0 + r0 + 2 * j]),
                              __float_as_int(v));
            }
        }
    } else {
        #pragma unroll
        for (int k = 0; k < 8; k++) {
            #pragma unroll
            for (int j = 0; j < 4; j++) {
                int idx = ((b * Cc + coBase + k) * 96 + h0 + r0 + 2 * j) * 96 +
                          w0 + cwl;
                float v = acc[k][j] * gv[k] + bv[k];
                if (EPI == 2) {
                    g_c1[idx] = v;                         // no act
                } else if (EPI == 3) {
                    g_relut[idx] = fmaxf(v + g_c1[idx], 0.f);
                } else {                                   // EPI == 4
                    outp[idx] = fmaxf(v, 0.f);
                }
            }
        }
    }
}

extern "C" void kernel_launch(void* const* d_in, const int* in_sizes, int n_in,
                              void* d_out, int out_size) {
    (void)in_sizes; (void)n_in; (void)out_size;
    const float* x     = (const float*)d_in[0];
    const float* w_p1  = (const float*)d_in[1];
    const float* gp1   = (const float*)d_in[2];
    const float* bp1   = (const float*)d_in[3];
    const float* w_p2  = (const float*)d_in[4];
    const float* gp2   = (const float*)d_in[5];
    const float* bp2   = (const float*)d_in[6];
    const float* w_p   = (const float*)d_in[7];
    const float* gp    = (const float*)d_in[8];
    const float* bp    = (const float*)d_in[9];
    const float* w_c1  = (const float*)d_in[10];
    const float* gc1   = (const float*)d_in[11];
    const float* bc1   = (const float*)d_in[12];
    const float* w_c2  = (const float*)d_in[13];
    const float* gc2   = (const float*)d_in[14];
    const float* bc2   = (const float*)d_in[15];
    float* out = (float*)d_out;

    zero_pools_kernel<<<(NPOOL + 255) / 256, 256>>>();
    int twb = (NW + 255) / 256;
    transform_w_kernel<<<twb, 256>>>(w_p1, 0);
    transform_w_kernel<<<twb, 256>>>(w_p2, 1);
    transform_w_kernel<<<twb, 256>>>(w_c1, 2);
    transform_w_kernel<<<twb, 256>>>(w_p,  3);
    transform_w_kernel<<<twb, 256>>>(w_c2, 4);

    dim3 grid(Ww / TWt, Hh / TH, Bn * (Cc / TCO));   // 6 x 12 x 32
    conv3x3_kernel<false, 0><<<grid, 256>>>(x,       0, gp1, bp1, nullptr);
    conv3x3_kernel<false, 1><<<grid, 256>>>(x,       1, gp2, bp2, nullptr);
    conv3x3_kernel<false, 2><<<grid, 256>>>(x,       2, gc1, bc1, nullptr);
    conv3x3_kernel<true,  3><<<grid, 256>>>(nullptr, 3, gp,  bp,  nullptr);
    conv3x3_kernel<false, 4><<<grid, 256>>>(nullptr, 4, gc2, bc2, out);
}

// round 10
// speedup vs baseline: 1.5934x; 1.5934x over previous
#include <cuda_runtime.h>
#include <cuda_pipeline.h>
#include <mma.h>
#include <cstdint>
#include <cstddef>

using namespace nvcuda;

// ============================================================================
// ct_layer via official wmma tf32 (no inline PTX anywhere):
// 5x conv3x3(256->256)+BN as shift-GEMMs over NHWC, pipelined double buffer.
// Corner pools collapse to global row/col maxes (cummax(rev);cummax(fwd) ==
// broadcast global max along the axis -- proven in R1).
// ============================================================================

constexpr int Bn = 8, Cc = 256, Hh = 96, Ww = 96;
constexpr size_t NTEN = (size_t)Bn * Hh * Ww * Cc;   // 18874368
constexpr int NW    = Cc * Cc * 9;                   // 589824
constexpr int NPOOL = Bn * 96 * Cc;                  // 196608

// Scratch device globals (g_xh doubles as psum buffer after the first 3 convs)
__device__ __align__(256) float g_xh[NTEN];      // x NHWC tf32  ->  psum
__device__ __align__(256) float g_relut[NTEN];   // relu(p_conv + conv1) tf32
__device__ __align__(256) float g_c1[NTEN];      // conv_c1 out (affine) fp32
__device__ __align__(256) float g_w2[5][NW];     // weights [k][co][ci] tf32
__device__ __align__(256) float g_colmax[NPOOL]; // [b][w][c]
__device__ __align__(256) float g_rowmax[NPOOL]; // [b][h][c]

__device__ __forceinline__ float tf32r(float x) {
    return wmma::__float_to_tf32(x);
}

// ---------------------------------------------------------------- prep kernels
__global__ void zero_pools_kernel() {
    int i = blockIdx.x * 256 + threadIdx.x;
    if (i < NPOOL) { g_colmax[i] = 0.f; g_rowmax[i] = 0.f; }
}

// NCHW -> NHWC with tf32 round (32c x 32w tiles per (b,h))
__global__ void xtrans_kernel(const float* __restrict__ x) {
    __shared__ float t[32][33];
    int b = blockIdx.z, h = blockIdx.y;
    int c0 = (blockIdx.x / 3) * 32, w0 = (blockIdx.x % 3) * 32;
    int tx = threadIdx.x & 31, ty = threadIdx.x >> 5;
    #pragma unroll
    for (int i = 0; i < 4; i++) {
        int c = ty + 8 * i;
        t[c][tx] = tf32r(x[(((size_t)b * Cc + c0 + c) * Hh + h) * Ww + w0 + tx]);
    }
    __syncthreads();
    #pragma unroll
    for (int i = 0; i < 4; i++) {
        int w = ty + 8 * i;
        g_xh[(((size_t)b * Hh + h) * Ww + w0 + w) * Cc + c0 + tx] = t[tx][w];
    }
}

// OIHW -> [k][co][ci] tf32
__global__ void wtrans_kernel(const float* __restrict__ src, int which) {
    int idx = blockIdx.x * 256 + threadIdx.x;
    if (idx < NW) {
        int ci = idx & 255, co = (idx >> 8) & 255, k = idx >> 16;
        g_w2[which][idx] = tf32r(src[((size_t)co * Cc + ci) * 9 + k]);
    }
}

// g_xh[b][h][w][c] = tf32(colmax[b][w][c] + rowmax[b][h][c])   (x is dead now)
__global__ void psum_kernel() {
    size_t e4 = ((size_t)blockIdx.x * 256 + threadIdx.x) * 4;
    int c = (int)(e4 & 255);
    size_t p = e4 >> 8;
    int w = (int)(p % 96); size_t p2 = p / 96;
    int h = (int)(p2 % 96); int b = (int)(p2 / 96);
    float4 cm = *(const float4*)&g_colmax[((size_t)b * 96 + w) * 256 + c];
    float4 rm = *(const float4*)&g_rowmax[((size_t)b * 96 + h) * 256 + c];
    float4 o;
    o.x = tf32r(cm.x + rm.x); o.y = tf32r(cm.y + rm.y);
    o.z = tf32r(cm.z + rm.z); o.w = tf32r(cm.w + rm.w);
    *(float4*)&g_xh[e4] = o;
}

// ---------------------------------------------------------------- conv kernel
// Tile: M=128 pixels (8h x 16w), N=64 couts.  K chunks of 16 (9 shifts x 16).
constexpr int APAD = 20;                 // pad 16->20: conflict-free, ldm%4==0
constexpr int A_FL  = 128 * APAD;        // 2560 floats
constexpr int B_FL  = 64 * APAD;         // 1280 floats
constexpr int STG_FL = A_FL + B_FL;      // 3840 floats (15360 B/stage)
constexpr int DPAD = 68;                 // D tile 128 x 68 floats = 34816 B
constexpr int SMRAW_B = 128 * DPAD * 4;  // 34816 >= 2*STG_FL*4 = 30720
constexpr int NCHUNK = 144;

// Load one K-chunk (cc = shift*16 + ch) into stage buffer s.
__device__ __forceinline__ void load_chunk(
    float* stage, const float* __restrict__ aSrc, const float* __restrict__ wSrc,
    int s, int cc, int b, int h0, int w0, int N0, int tid)
{
    const int shift = cc >> 4, ch = cc & 15;
    const int dh = shift / 3 - 1, dw = (shift % 3) - 1;
    float* As = stage + s * STG_FL;
    float* Bs = As + A_FL;
    // ---- A: row = tid (pixel), 16 floats = 4 x 16B (OOB rows zero-filled) ----
    {
        const int hl = tid >> 4, wl = tid & 15;
        const int h = h0 + hl + dh, w = w0 + wl + dw;
        const bool inb = ((unsigned)h < 96u) & ((unsigned)w < 96u);
        const size_t zf = inb ? 0u : 16u;
        const float* gp = aSrc +
            ((((size_t)b * Hh + (inb ? h : 0)) * Ww + (inb ? w : 0)) * Cc + ch * 16);
        float* dp = As + tid * APAD;
        #pragma unroll
        for (int q = 0; q < 4; q++)
            __pipeline_memcpy_async(dp + q * 4, gp + q * 4, 16, zf);
    }
    // ---- B: 64 rows x 16 floats; thread t: row t>>1, half t&1 (2 x 16B) ----
    {
        const int row = tid >> 1, half = tid & 1;
        const float* gp = wSrc +
            (((size_t)shift * 256 + N0 + row) * 256 + ch * 16 + half * 8);
        float* dp = Bs + row * APAD + half * 8;
        __pipeline_memcpy_async(dp,     gp,     16, 0);
        __pipeline_memcpy_async(dp + 4, gp + 4, 16, 0);
    }
}

// EPI: 0 colmax, 1 rowmax, 2 store c1, 3 +c1 relu -> relut, 4 relu -> NCHW out
template <int EPI>
__global__ __launch_bounds__(128, 4) void conv_mma_kernel(
    int widx, const float* __restrict__ gg, const float* __restrict__ bb,
    float* __restrict__ outp)
{
    __shared__ __align__(16) char smraw[SMRAW_B];   // stages overlay D tile
    __shared__ float gb_s[128];
    float* stage = (float*)smraw;
    float* Ds    = (float*)smraw;

    const int tid = threadIdx.x, wid = tid >> 5;
    const int w0 = blockIdx.x * 16, h0 = blockIdx.y * 8;
    const int b = blockIdx.z >> 2, N0 = (blockIdx.z & 3) * 64;

    const float* aSrc = (EPI == 4) ? g_relut : g_xh;  // EPI3 reads psum (in g_xh)
    const float* wSrc = g_w2[widx];
    gb_s[tid] = (tid < 64) ? gg[N0 + tid] : bb[N0 + tid - 64];

    // warp tile: rows [wid*32, wid*32+32), all 64 cols -> 2x4 fragments
    wmma::fragment<wmma::accumulator, 16, 16, 8, float> acc[2][4];
    #pragma unroll
    for (int i = 0; i < 2; i++)
        #pragma unroll
        for (int j = 0; j < 4; j++) wmma::fill_fragment(acc[i][j], 0.f);
    const int m0 = wid * 32;

    load_chunk(stage, aSrc, wSrc, 0, 0, b, h0, w0, N0, tid);
    __pipeline_commit();

    for (int cc = 0; cc < NCHUNK; cc++) {
        const int s = cc & 1;
        if (cc + 1 < NCHUNK) {
            load_chunk(stage, aSrc, wSrc, s ^ 1, cc + 1, b, h0, w0, N0, tid);
            __pipeline_commit();
            __pipeline_wait_prior(1);
        } else {
            __pipeline_wait_prior(0);
        }
        __syncthreads();

        const float* As = stage + s * STG_FL;
        const float* Bs = As + A_FL;
        #pragma unroll
        for (int k = 0; k < 2; k++) {
            wmma::fragment<wmma::matrix_a, 16, 16, 8, wmma::precision::tf32,
                           wmma::row_major> af[2];
            wmma::fragment<wmma::matrix_b, 16, 16, 8, wmma::precision::tf32,
                           wmma::col_major> bf[4];
            #pragma unroll
            for (int i = 0; i < 2; i++)
                wmma::load_matrix_sync(af[i], As + (m0 + i * 16) * APAD + k * 8, APAD);
            #pragma unroll
            for (int j = 0; j < 4; j++)
                wmma::load_matrix_sync(bf[j], Bs + (j * 16) * APAD + k * 8, APAD);
            #pragma unroll
            for (int i = 0; i < 2; i++)
                #pragma unroll
                for (int j = 0; j < 4; j++)
                    wmma::mma_sync(acc[i][j], af[i], bf[j], acc[i][j]);
        }
        __syncthreads();
    }

    // -------- write accumulators to smem D (overlays dead stage memory) ------
    #pragma unroll
    for (int i = 0; i < 2; i++)
        #pragma unroll
        for (int j = 0; j < 4; j++)
            wmma::store_matrix_sync(Ds + (m0 + i * 16) * DPAD + j * 16,
                                    acc[i][j], DPAD, wmma::mem_row_major);
    __syncthreads();

    // -------- epilogue --------
    if (EPI == 0) {
        // colmax[b][w][c]: max over the 8 h-rows; atomicMax vs 0-init buffer
        // (implicit relu: max(0, max_h a) == max_h relu(a))
        #pragma unroll
        for (int i = 0; i < 8; i++) {
            int p = tid * 8 + i;
            int wl = p >> 6, c = p & 63;
            float gsc = gb_s[c], bsc = gb_s[64 + c];
            float m = -1e30f;
            #pragma unroll
            for (int hl = 0; hl < 8; hl++)
                m = fmaxf(m, Ds[(hl * 16 + wl) * DPAD + c] * gsc + bsc);
            atomicMax((int*)&g_colmax[((size_t)b * Ww + w0 + wl) * Cc + N0 + c],
                      __float_as_int(m));
        }
    } else if (EPI == 1) {
        // rowmax[b][h][c]: max over the 16 w-cols
        #pragma unroll
        for (int i = 0; i < 4; i++) {
            int p = tid * 4 + i;
            int hl = p >> 6, c = p & 63;
            float gsc = gb_s[c], bsc = gb_s[64 + c];
            float m = -1e30f;
            #pragma unroll
            for (int wl = 0; wl < 16; wl++)
                m = fmaxf(m, Ds[(hl * 16 + wl) * DPAD + c] * gsc + bsc);
            atomicMax((int*)&g_rowmax[((size_t)b * Hh + h0 + hl) * Cc + N0 + c],
                      __float_as_int(m));
        }
    } else {
        const int hl = tid >> 4, wl = tid & 15;
        const size_t pix = ((size_t)b * Hh + h0 + hl) * Ww + (w0 + wl);
        const float* dr = Ds + tid * DPAD;
        if (EPI == 2) {
            #pragma unroll
            for (int c = 0; c < 64; c += 4) {
                float4 v;
                v.x = dr[c+0] * gb_s[c+0] + gb_s[64+c+0];
                v.y = dr[c+1] * gb_s[c+1] + gb_s[64+c+1];
                v.z = dr[c+2] * gb_s[c+2] + gb_s[64+c+2];
                v.w = dr[c+3] * gb_s[c+3] + gb_s[64+c+3];
                *(float4*)&g_c1[pix * Cc + N0 + c] = v;
            }
        } else if (EPI == 3) {
            #pragma unroll
            for (int c = 0; c < 64; c += 4) {
                float4 c1v = *(const float4*)&g_c1[pix * Cc + N0 + c];
                float4 v;
                v.x = tf32r(fmaxf(dr[c+0] * gb_s[c+0] + gb_s[64+c+0] + c1v.x, 0.f));
                v.y = tf32r(fmaxf(dr[c+1] * gb_s[c+1] + gb_s[64+c+1] + c1v.y, 0.f));
                v.z = tf32r(fmaxf(dr[c+2] * gb_s[c+2] + gb_s[64+c+2] + c1v.z, 0.f));
                v.w = tf32r(fmaxf(dr[c+3] * gb_s[c+3] + gb_s[64+c+3] + c1v.w, 0.f));
                *(float4*)&g_relut[pix * Cc + N0 + c] = v;
            }
        } else {   // EPI 4: final conv, relu, NCHW output
            const int h = h0 + hl, w = w0 + wl;
            #pragma unroll
            for (int c = 0; c < 64; c++) {
                float v = fmaxf(dr[c] * gb_s[c] + gb_s[64 + c], 0.f);
                outp[(((size_t)b * Cc + N0 + c) * Hh + h) * Ww + w] = v;
            }
        }
    }
}

// ---------------------------------------------------------------- host
extern "C" void kernel_launch(void* const* d_in, const int* in_sizes, int n_in,
                              void* d_out, int out_size) {
    (void)in_sizes; (void)n_in; (void)out_size;
    const float* x    = (const float*)d_in[0];
    const float* w_p1 = (const float*)d_in[1];
    const float* gp1  = (const float*)d_in[2];
    const float* bp1  = (const float*)d_in[3];
    const float* w_p2 = (const float*)d_in[4];
    const float* gp2  = (const float*)d_in[5];
    const float* bp2  = (const float*)d_in[6];
    const float* w_p  = (const float*)d_in[7];
    const float* gp   = (const float*)d_in[8];
    const float* bp   = (const float*)d_in[9];
    const float* w_c1 = (const float*)d_in[10];
    const float* gc1  = (const float*)d_in[11];
    const float* bc1  = (const float*)d_in[12];
    const float* w_c2 = (const float*)d_in[13];
    const float* gc2  = (const float*)d_in[14];
    const float* bc2  = (const float*)d_in[15];
    float* out = (float*)d_out;

    zero_pools_kernel<<<(NPOOL + 255) / 256, 256>>>();
    xtrans_kernel<<<dim3(24, 96, 8), 256>>>(x);
    int twb = (NW + 255) / 256;
    wtrans_kernel<<<twb, 256>>>(w_p1, 0);
    wtrans_kernel<<<twb, 256>>>(w_p2, 1);
    wtrans_kernel<<<twb, 256>>>(w_c1, 2);
    wtrans_kernel<<<twb, 256>>>(w_p,  3);
    wtrans_kernel<<<twb, 256>>>(w_c2, 4);

    dim3 grid(Ww / 16, Hh / 8, Bn * 4);   // 6 x 12 x 32 = 2304 CTAs
    conv_mma_kernel<0><<<grid, 128>>>(0, gp1, bp1, nullptr);
    conv_mma_kernel<1><<<grid, 128>>>(1, gp2, bp2, nullptr);
    conv_mma_kernel<2><<<grid, 128>>>(2, gc1, bc1, nullptr);
    psum_kernel<<<(int)(NTEN / 4 / 256), 256>>>();   // writes psum into g_xh
    conv_mma_kernel<3><<<grid, 128>>>(3, gp,  bp,  nullptr);
    conv_mma_kernel<4><<<grid, 128>>>(4, gc2, bc2, out);
}

// round 11
// speedup vs baseline: 1.6947x; 1.0635x over previous
#include <cuda_runtime.h>
#include <cuda_pipeline.h>
#include <mma.h>
#include <cstdint>
#include <cstddef>

using namespace nvcuda;

// ============================================================================
// ct_layer via official wmma tf32 (no inline PTX, static smem <= 48KB):
// 5x conv3x3(256->256)+BN as shift-GEMMs over NHWC, pipelined double buffer.
// CTA tile M=128 pixels x N=128 couts, warp tile M64xN64 (2x2 warps).
// Corner pools collapse to global row/col maxes (proven R1).
// ============================================================================

constexpr int Bn = 8, Cc = 256, Hh = 96, Ww = 96;
constexpr size_t NTEN = (size_t)Bn * Hh * Ww * Cc;   // 18874368
constexpr int NW    = Cc * Cc * 9;                   // 589824
constexpr int NPOOL = Bn * 96 * Cc;                  // 196608

__device__ __align__(256) float g_xh[NTEN];      // x NHWC tf32  ->  psum
__device__ __align__(256) float g_relut[NTEN];   // relu(p_conv + conv1) tf32
__device__ __align__(256) float g_c1[NTEN];      // conv_c1 out (affine) fp32
__device__ __align__(256) float g_w2[5][NW];     // weights [k][co][ci] tf32
__device__ __align__(256) float g_colmax[NPOOL]; // [b][w][c]
__device__ __align__(256) float g_rowmax[NPOOL]; // [b][h][c]

__device__ __forceinline__ float tf32r(float x) {
    return wmma::__float_to_tf32(x);
}

// ---------------------------------------------------------------- prep kernels
__global__ void zero_pools_kernel() {
    int i = blockIdx.x * 256 + threadIdx.x;
    if (i < NPOOL) { g_colmax[i] = 0.f; g_rowmax[i] = 0.f; }
}

// NCHW -> NHWC with tf32 round (32c x 32w tiles per (b,h))
__global__ void xtrans_kernel(const float* __restrict__ x) {
    __shared__ float t[32][33];
    int b = blockIdx.z, h = blockIdx.y;
    int c0 = (blockIdx.x / 3) * 32, w0 = (blockIdx.x % 3) * 32;
    int tx = threadIdx.x & 31, ty = threadIdx.x >> 5;
    #pragma unroll
    for (int i = 0; i < 4; i++) {
        int c = ty + 8 * i;
        t[c][tx] = tf32r(x[(((size_t)b * Cc + c0 + c) * Hh + h) * Ww + w0 + tx]);
    }
    __syncthreads();
    #pragma unroll
    for (int i = 0; i < 4; i++) {
        int w = ty + 8 * i;
        g_xh[(((size_t)b * Hh + h) * Ww + w0 + w) * Cc + c0 + tx] = t[tx][w];
    }
}

// OIHW -> [k][co][ci] tf32
__global__ void wtrans_kernel(const float* __restrict__ src, int which) {
    int idx = blockIdx.x * 256 + threadIdx.x;
    if (idx < NW) {
        int ci = idx & 255, co = (idx >> 8) & 255, k = idx >> 16;
        g_w2[which][idx] = tf32r(src[((size_t)co * Cc + ci) * 9 + k]);
    }
}

// g_xh[b][h][w][c] = tf32(colmax[b][w][c] + rowmax[b][h][c])   (x is dead now)
__global__ void psum_kernel() {
    size_t e4 = ((size_t)blockIdx.x * 256 + threadIdx.x) * 4;
    int c = (int)(e4 & 255);
    size_t p = e4 >> 8;
    int w = (int)(p % 96); size_t p2 = p / 96;
    int h = (int)(p2 % 96); int b = (int)(p2 / 96);
    float4 cm = *(const float4*)&g_colmax[((size_t)b * 96 + w) * 256 + c];
    float4 rm = *(const float4*)&g_rowmax[((size_t)b * 96 + h) * 256 + c];
    float4 o;
    o.x = tf32r(cm.x + rm.x); o.y = tf32r(cm.y + rm.y);
    o.z = tf32r(cm.z + rm.z); o.w = tf32r(cm.w + rm.w);
    *(float4*)&g_xh[e4] = o;
}

// ---------------------------------------------------------------- conv kernel
constexpr int APAD = 20;                 // K=16 padded to 20: conflict-free
constexpr int A_FL  = 128 * APAD;        // 2560 floats
constexpr int B_FL  = 128 * APAD;        // 2560 floats (N=128 couts)
constexpr int STG_FL = A_FL + B_FL;      // 5120 floats (20480 B/stage)
constexpr int DPAD = 68;                 // D half-tile: 128 x 68 fl = 34816 B
constexpr int SMRAW_B = 2 * STG_FL * 4;  // 40960 B (>= D half-tile)
constexpr int NCHUNK = 144;              // 9 shifts x 16 cin-chunks of 16

// Load one K-chunk (cc = shift*16 + ch) into stage buffer s.
__device__ __forceinline__ void load_chunk(
    float* stage, const float* __restrict__ aSrc, const float* __restrict__ wSrc,
    int s, int cc, int b, int h0, int w0, int N0, int tid)
{
    const int shift = cc >> 4, ch = cc & 15;
    const int dh = shift / 3 - 1, dw = (shift % 3) - 1;
    float* As = stage + s * STG_FL;
    float* Bs = As + A_FL;
    // ---- A: row = tid (pixel), 16 floats = 4 x 16B (OOB rows zero-filled) ----
    {
        const int hl = tid >> 4, wl = tid & 15;
        const int h = h0 + hl + dh, w = w0 + wl + dw;
        const bool inb = ((unsigned)h < 96u) & ((unsigned)w < 96u);
        const size_t zf = inb ? 0u : 16u;
        const float* gp = aSrc +
            ((((size_t)b * Hh + (inb ? h : 0)) * Ww + (inb ? w : 0)) * Cc + ch * 16);
        float* dp = As + tid * APAD;
        #pragma unroll
        for (int q = 0; q < 4; q++)
            __pipeline_memcpy_async(dp + q * 4, gp + q * 4, 16, zf);
    }
    // ---- B: 128 rows (couts) x 16 floats; thread t: row t ----
    {
        const float* gp = wSrc + (((size_t)shift * 256 + N0 + tid) * 256 + ch * 16);
        float* dp = Bs + tid * APAD;
        #pragma unroll
        for (int q = 0; q < 4; q++)
            __pipeline_memcpy_async(dp + q * 4, gp + q * 4, 16, 0);
    }
}

// EPI: 0 colmax, 1 rowmax, 2 store c1, 3 +c1 relu -> relut, 4 relu -> NCHW out
template <int EPI>
__global__ __launch_bounds__(128, 2) void conv_mma_kernel(
    int widx, const float* __restrict__ gg, const float* __restrict__ bb,
    float* __restrict__ outp)
{
    __shared__ __align__(16) char smraw[SMRAW_B];   // stages overlay D tile
    __shared__ float gb_s[256];
    float* stage = (float*)smraw;
    float* Ds    = (float*)smraw;

    const int tid = threadIdx.x, wid = tid >> 5;
    const int warp_m = wid >> 1, warp_n = wid & 1;     // 2x2 warp grid
    const int w0 = blockIdx.x * 16, h0 = blockIdx.y * 8;
    const int b = blockIdx.z >> 1, N0 = (blockIdx.z & 1) * 128;

    const float* aSrc = (EPI == 4) ? g_relut : g_xh;  // EPI3 reads psum (in g_xh)
    const float* wSrc = g_w2[widx];
    gb_s[tid]       = gg[N0 + tid];
    gb_s[128 + tid] = bb[N0 + tid];

    // warp tile M64 x N64: 4x4 accumulator fragments
    wmma::fragment<wmma::accumulator, 16, 16, 8, float> acc[4][4];
    #pragma unroll
    for (int i = 0; i < 4; i++)
        #pragma unroll
        for (int j = 0; j < 4; j++) wmma::fill_fragment(acc[i][j], 0.f);
    const int m0 = warp_m * 64, n0 = warp_n * 64;

    load_chunk(stage, aSrc, wSrc, 0, 0, b, h0, w0, N0, tid);
    __pipeline_commit();

    for (int cc = 0; cc < NCHUNK; cc++) {
        const int s = cc & 1;
        __pipeline_wait_prior(0);     // stage s data landed
        __syncthreads();              // + everyone done computing stage s^1
        if (cc + 1 < NCHUNK) {
            load_chunk(stage, aSrc, wSrc, s ^ 1, cc + 1, b, h0, w0, N0, tid);
            __pipeline_commit();      // overlaps with compute below
        }
        const float* As = stage + s * STG_FL;
        const float* Bs = As + A_FL;
        #pragma unroll
        for (int k = 0; k < 2; k++) {
            wmma::fragment<wmma::matrix_a, 16, 16, 8, wmma::precision::tf32,
                           wmma::row_major> af[4];
            wmma::fragment<wmma::matrix_b, 16, 16, 8, wmma::precision::tf32,
                           wmma::col_major> bf[4];
            #pragma unroll
            for (int i = 0; i < 4; i++)
                wmma::load_matrix_sync(af[i], As + (m0 + i * 16) * APAD + k * 8, APAD);
            #pragma unroll
            for (int j = 0; j < 4; j++)
                wmma::load_matrix_sync(bf[j], Bs + (n0 + j * 16) * APAD + k * 8, APAD);
            #pragma unroll
            for (int i = 0; i < 4; i++)
                #pragma unroll
                for (int j = 0; j < 4; j++)
                    wmma::mma_sync(acc[i][j], af[i], bf[j], acc[i][j]);
        }
    }
    __syncthreads();   // mainloop done; stage smem becomes the D tile

    // -------- epilogue: two passes over the N halves --------
    #pragma unroll
    for (int half = 0; half < 2; half++) {
        if (warp_n == half) {
            #pragma unroll
            for (int i = 0; i < 4; i++)
                #pragma unroll
                for (int j = 0; j < 4; j++)
                    wmma::store_matrix_sync(Ds + (m0 + i * 16) * DPAD + j * 16,
                                            acc[i][j], DPAD, wmma::mem_row_major);
        }
        __syncthreads();
        const int N0h = N0 + half * 64;
        const int gbo = half * 64;

        if (EPI == 0) {
            // colmax[b][w][c]: max over 8 h-rows; atomicMax vs 0-init buffer
            #pragma unroll
            for (int i = 0; i < 8; i++) {
                int p = tid * 8 + i;
                int wl = p >> 6, c = p & 63;
                float gsc = gb_s[gbo + c], bsc = gb_s[128 + gbo + c];
                float m = -1e30f;
                #pragma unroll
                for (int hl = 0; hl < 8; hl++)
                    m = fmaxf(m, Ds[(hl * 16 + wl) * DPAD + c] * gsc + bsc);
                atomicMax((int*)&g_colmax[((size_t)b * Ww + w0 + wl) * Cc + N0h + c],
                          __float_as_int(m));
            }
        } else if (EPI == 1) {
            // rowmax[b][h][c]: max over 16 w-cols
            #pragma unroll
            for (int i = 0; i < 4; i++) {
                int p = tid * 4 + i;
                int hl = p >> 6, c = p & 63;
                float gsc = gb_s[gbo + c], bsc = gb_s[128 + gbo + c];
                float m = -1e30f;
                #pragma unroll
                for (int wl = 0; wl < 16; wl++)
                    m = fmaxf(m, Ds[(hl * 16 + wl) * DPAD + c] * gsc + bsc);
                atomicMax((int*)&g_rowmax[((size_t)b * Hh + h0 + hl) * Cc + N0h + c],
                          __float_as_int(m));
            }
        } else {
            const int hl = tid >> 4, wl = tid & 15;
            const size_t pix = ((size_t)b * Hh + h0 + hl) * Ww + (w0 + wl);
            const float* dr = Ds + tid * DPAD;
            if (EPI == 2) {
                #pragma unroll
                for (int c = 0; c < 64; c += 4) {
                    float4 v;
                    v.x = dr[c+0] * gb_s[gbo+c+0] + gb_s[128+gbo+c+0];
                    v.y = dr[c+1] * gb_s[gbo+c+1] + gb_s[128+gbo+c+1];
                    v.z = dr[c+2] * gb_s[gbo+c+2] + gb_s[128+gbo+c+2];
                    v.w = dr[c+3] * gb_s[gbo+c+3] + gb_s[128+gbo+c+3];
                    *(float4*)&g_c1[pix * Cc + N0h + c] = v;
                }
            } else if (EPI == 3) {
                #pragma unroll
                for (int c = 0; c < 64; c += 4) {
                    float4 c1v = *(const float4*)&g_c1[pix * Cc + N0h + c];
                    float4 v;
                    v.x = tf32r(fmaxf(dr[c+0] * gb_s[gbo+c+0] + gb_s[128+gbo+c+0] + c1v.x, 0.f));
                    v.y = tf32r(fmaxf(dr[c+1] * gb_s[gbo+c+1] + gb_s[128+gbo+c+1] + c1v.y, 0.f));
                    v.z = tf32r(fmaxf(dr[c+2] * gb_s[gbo+c+2] + gb_s[128+gbo+c+2] + c1v.z, 0.f));
                    v.w = tf32r(fmaxf(dr[c+3] * gb_s[gbo+c+3] + gb_s[128+gbo+c+3] + c1v.w, 0.f));
                    *(float4*)&g_relut[pix * Cc + N0h + c] = v;
                }
            } else {   // EPI 4: final conv, relu, NCHW output
                const int h = h0 + hl, w = w0 + wl;
                #pragma unroll
                for (int c = 0; c < 64; c++) {
                    float v = fmaxf(dr[c] * gb_s[gbo + c] + gb_s[128 + gbo + c], 0.f);
                    outp[(((size_t)b * Cc + N0h + c) * Hh + h) * Ww + w] = v;
                }
            }
        }
        __syncthreads();   // protect Ds before next half overwrites it
    }
}

// ---------------------------------------------------------------- host
extern "C" void kernel_launch(void* const* d_in, const int* in_sizes, int n_in,
                              void* d_out, int out_size) {
    (void)in_sizes; (void)n_in; (void)out_size;
    const float* x    = (const float*)d_in[0];
    const float* w_p1 = (const float*)d_in[1];
    const float* gp1  = (const float*)d_in[2];
    const float* bp1  = (const float*)d_in[3];
    const float* w_p2 = (const float*)d_in[4];
    const float* gp2  = (const float*)d_in[5];
    const float* bp2  = (const float*)d_in[6];
    const float* w_p  = (const float*)d_in[7];
    const float* gp   = (const float*)d_in[8];
    const float* bp   = (const float*)d_in[9];
    const float* w_c1 = (const float*)d_in[10];
    const float* gc1  = (const float*)d_in[11];
    const float* bc1  = (const float*)d_in[12];
    const float* w_c2 = (const float*)d_in[13];
    const float* gc2  = (const float*)d_in[14];
    const float* bc2  = (const float*)d_in[15];
    float* out = (float*)d_out;

    zero_pools_kernel<<<(NPOOL + 255) / 256, 256>>>();
    xtrans_kernel<<<dim3(24, 96, 8), 256>>>(x);
    int twb = (NW + 255) / 256;
    wtrans_kernel<<<twb, 256>>>(w_p1, 0);
    wtrans_kernel<<<twb, 256>>>(w_p2, 1);
    wtrans_kernel<<<twb, 256>>>(w_c1, 2);
    wtrans_kernel<<<twb, 256>>>(w_p,  3);
    wtrans_kernel<<<twb, 256>>>(w_c2, 4);

    dim3 grid(Ww / 16, Hh / 8, Bn * 2);   // 6 x 12 x 16 = 1152 CTAs
    conv_mma_kernel<0><<<grid, 128>>>(0, gp1, bp1, nullptr);
    conv_mma_kernel<1><<<grid, 128>>>(1, gp2, bp2, nullptr);
    conv_mma_kernel<2><<<grid, 128>>>(2, gc1, bc1, nullptr);
    psum_kernel<<<(int)(NTEN / 4 / 256), 256>>>();   // writes psum into g_xh
    conv_mma_kernel<3><<<grid, 128>>>(3, gp,  bp,  nullptr);
    conv_mma_kernel<4><<<grid, 128>>>(4, gc2, bc2, out);
}

// round 12
// speedup vs baseline: 6.0381x; 3.5630x over previous
#include <cuda_runtime.h>
#include <cuda_pipeline.h>
#include <cuda_fp16.h>
#include <mma.h>
#include <cstdint>
#include <cstddef>

using namespace nvcuda;

// ============================================================================
// ct_layer via wmma fp16 (f32 accumulate), no inline PTX, static smem <=48KB:
// 5x conv3x3(256->256)+BN as shift-GEMMs over NHWC, pipelined double buffer.
// CTA tile M=128 pixels x N=128 couts, warp tile M64xN64 (2x2 warps).
// Corner pools collapse to global row/col maxes (proven R1).
// ============================================================================

constexpr int Bn = 8, Cc = 256, Hh = 96, Ww = 96;
constexpr size_t NTEN = (size_t)Bn * Hh * Ww * Cc;   // 18874368
constexpr int NW    = Cc * Cc * 9;                   // 589824
constexpr int NPOOL = Bn * 96 * Cc;                  // 196608

__device__ __align__(256) __half g_xh[NTEN];     // x NHWC fp16  ->  psum
__device__ __align__(256) __half g_relut[NTEN];  // relu(p_conv + conv1) fp16
__device__ __align__(256) float  g_c1[NTEN];     // conv_c1 out (affine) fp32
__device__ __align__(256) __half g_w2[5][NW];    // weights [k][co][ci] fp16
__device__ __align__(256) float  g_colmax[NPOOL];// [b][w][c]
__device__ __align__(256) float  g_rowmax[NPOOL];// [b][h][c]

// ---------------------------------------------------------------- prep kernels
__global__ void zero_pools_kernel() {
    int i = blockIdx.x * 256 + threadIdx.x;
    if (i < NPOOL) { g_colmax[i] = 0.f; g_rowmax[i] = 0.f; }
}

// NCHW fp32 -> NHWC fp16 (32c x 32w tiles per (b,h))
__global__ void xtrans_kernel(const float* __restrict__ x) {
    __shared__ float t[32][33];
    int b = blockIdx.z, h = blockIdx.y;
    int c0 = (blockIdx.x / 3) * 32, w0 = (blockIdx.x % 3) * 32;
    int tx = threadIdx.x & 31, ty = threadIdx.x >> 5;
    #pragma unroll
    for (int i = 0; i < 4; i++) {
        int c = ty + 8 * i;
        t[c][tx] = x[(((size_t)b * Cc + c0 + c) * Hh + h) * Ww + w0 + tx];
    }
    __syncthreads();
    #pragma unroll
    for (int i = 0; i < 4; i++) {
        int w = ty + 8 * i;
        g_xh[(((size_t)b * Hh + h) * Ww + w0 + w) * Cc + c0 + tx] =
            __float2half_rn(t[tx][w]);
    }
}

// OIHW fp32 -> [k][co][ci] fp16
__global__ void wtrans_kernel(const float* __restrict__ src, int which) {
    int idx = blockIdx.x * 256 + threadIdx.x;
    if (idx < NW) {
        int ci = idx & 255, co = (idx >> 8) & 255, k = idx >> 16;
        g_w2[which][idx] = __float2half_rn(src[((size_t)co * Cc + ci) * 9 + k]);
    }
}

// g_xh[b][h][w][c] = fp16(colmax[b][w][c] + rowmax[b][h][c])   (x is dead now)
__global__ void psum_kernel() {
    size_t e8 = ((size_t)blockIdx.x * 256 + threadIdx.x) * 8;
    int c = (int)(e8 & 255);
    size_t p = e8 >> 8;
    int w = (int)(p % 96); size_t p2 = p / 96;
    int h = (int)(p2 % 96); int b = (int)(p2 / 96);
    const float* cm = &g_colmax[((size_t)b * 96 + w) * 256 + c];
    const float* rm = &g_rowmax[((size_t)b * 96 + h) * 256 + c];
    __half hv[8];
    #pragma unroll
    for (int i = 0; i < 8; i++) hv[i] = __float2half_rn(cm[i] + rm[i]);
    *(uint4*)&g_xh[e8] = *(const uint4*)hv;
}

// ---------------------------------------------------------------- conv kernel
// K chunks of 32 channels: 9 shifts x 8 cin-chunks = 72 chunks.
constexpr int APAD = 40;                 // halves; row = 80B (conflict-free)
constexpr int A_H  = 128 * APAD;         // 5120 halves (10240 B)
constexpr int B_H  = 128 * APAD;         // 5120 halves
constexpr int STG_H = A_H + B_H;         // 10240 halves (20480 B/stage)
constexpr int DPAD = 68;                 // D half-tile: 128 x 68 fl = 34816 B
constexpr int SMRAW_B = 2 * STG_H * 2;   // 40960 B (>= D half-tile)
constexpr int NCHUNK = 72;

// Load one K-chunk (cc = shift*8 + ch) into stage buffer s.
__device__ __forceinline__ void load_chunk(
    __half* stage, const __half* __restrict__ aSrc, const __half* __restrict__ wSrc,
    int s, int cc, int b, int h0, int w0, int N0, int tid)
{
    const int shift = cc >> 3, ch = cc & 7;
    const int dh = shift / 3 - 1, dw = (shift % 3) - 1;
    __half* As = stage + s * STG_H;
    __half* Bs = As + A_H;
    // ---- A: row = tid (pixel), 32 halves = 4 x 16B (OOB rows zero-filled) ---
    {
        const int hl = tid >> 4, wl = tid & 15;
        const int h = h0 + hl + dh, w = w0 + wl + dw;
        const bool inb = ((unsigned)h < 96u) & ((unsigned)w < 96u);
        const size_t zf = inb ? 0u : 16u;
        const __half* gp = aSrc +
            ((((size_t)b * Hh + (inb ? h : 0)) * Ww + (inb ? w : 0)) * Cc + ch * 32);
        __half* dp = As + tid * APAD;
        #pragma unroll
        for (int q = 0; q < 4; q++)
            __pipeline_memcpy_async(dp + q * 8, gp + q * 8, 16, zf);
    }
    // ---- B: 128 rows (couts) x 32 halves; thread t: row t ----
    {
        const __half* gp = wSrc + (((size_t)shift * 256 + N0 + tid) * 256 + ch * 32);
        __half* dp = Bs + tid * APAD;
        #pragma unroll
        for (int q = 0; q < 4; q++)
            __pipeline_memcpy_async(dp + q * 8, gp + q * 8, 16, 0);
    }
}

// EPI: 0 colmax, 1 rowmax, 2 store c1, 3 +c1 relu -> relut, 4 relu -> NCHW out
template <int EPI>
__global__ __launch_bounds__(128, 2) void conv_mma_kernel(
    int widx, const float* __restrict__ gg, const float* __restrict__ bb,
    float* __restrict__ outp)
{
    __shared__ __align__(16) char smraw[SMRAW_B];   // stages overlay D tile
    __shared__ float gb_s[256];
    __half* stage = (__half*)smraw;
    float*  Ds    = (float*)smraw;

    const int tid = threadIdx.x, wid = tid >> 5;
    const int warp_m = wid >> 1, warp_n = wid & 1;     // 2x2 warp grid
    const int w0 = blockIdx.x * 16, h0 = blockIdx.y * 8;
    const int b = blockIdx.z >> 1, N0 = (blockIdx.z & 1) * 128;

    const __half* aSrc = (EPI == 4) ? g_relut : g_xh;  // EPI3 reads psum (g_xh)
    const __half* wSrc = g_w2[widx];
    gb_s[tid]       = gg[N0 + tid];
    gb_s[128 + tid] = bb[N0 + tid];

    // warp tile M64 x N64: 4x4 accumulator fragments (f32)
    wmma::fragment<wmma::accumulator, 16, 16, 16, float> acc[4][4];
    #pragma unroll
    for (int i = 0; i < 4; i++)
        #pragma unroll
        for (int j = 0; j < 4; j++) wmma::fill_fragment(acc[i][j], 0.f);
    const int m0 = warp_m * 64, n0 = warp_n * 64;

    load_chunk(stage, aSrc, wSrc, 0, 0, b, h0, w0, N0, tid);
    __pipeline_commit();

    for (int cc = 0; cc < NCHUNK; cc++) {
        const int s = cc & 1;
        __pipeline_wait_prior(0);     // stage s data landed
        __syncthreads();              // + everyone done computing stage s^1
        if (cc + 1 < NCHUNK) {
            load_chunk(stage, aSrc, wSrc, s ^ 1, cc + 1, b, h0, w0, N0, tid);
            __pipeline_commit();      // overlaps with compute below
        }
        const __half* As = stage + s * STG_H;
        const __half* Bs = As + A_H;
        #pragma unroll
        for (int k = 0; k < 2; k++) {
            wmma::fragment<wmma::matrix_a, 16, 16, 16, __half,
                           wmma::row_major> af[4];
            wmma::fragment<wmma::matrix_b, 16, 16, 16, __half,
                           wmma::col_major> bf[4];
            #pragma unroll
            for (int i = 0; i < 4; i++)
                wmma::load_matrix_sync(af[i], As + (m0 + i * 16) * APAD + k * 16, APAD);
            #pragma unroll
            for (int j = 0; j < 4; j++)
                wmma::load_matrix_sync(bf[j], Bs + (n0 + j * 16) * APAD + k * 16, APAD);
            #pragma unroll
            for (int i = 0; i < 4; i++)
                #pragma unroll
                for (int j = 0; j < 4; j++)
                    wmma::mma_sync(acc[i][j], af[i], bf[j], acc[i][j]);
        }
    }
    __syncthreads();   // mainloop done; stage smem becomes the D tile

    // -------- epilogue: two passes over the N halves --------
    #pragma unroll
    for (int half = 0; half < 2; half++) {
        if (warp_n == half) {
            #pragma unroll
            for (int i = 0; i < 4; i++)
                #pragma unroll
                for (int j = 0; j < 4; j++)
                    wmma::store_matrix_sync(Ds + (m0 + i * 16) * DPAD + j * 16,
                                            acc[i][j], DPAD, wmma::mem_row_major);
        }
        __syncthreads();
        const int N0h = N0 + half * 64;
        const int gbo = half * 64;

        if (EPI == 0) {
            // colmax[b][w][c]: max over 8 h-rows; atomicMax vs 0-init buffer
            #pragma unroll
            for (int i = 0; i < 8; i++) {
                int p = tid * 8 + i;
                int wl = p >> 6, c = p & 63;
                float gsc = gb_s[gbo + c], bsc = gb_s[128 + gbo + c];
                float m = -1e30f;
                #pragma unroll
                for (int hl = 0; hl < 8; hl++)
                    m = fmaxf(m, Ds[(hl * 16 + wl) * DPAD + c] * gsc + bsc);
                atomicMax((int*)&g_colmax[((size_t)b * Ww + w0 + wl) * Cc + N0h + c],
                          __float_as_int(m));
            }
        } else if (EPI == 1) {
            // rowmax[b][h][c]: max over 16 w-cols
            #pragma unroll
            for (int i = 0; i < 4; i++) {
                int p = tid * 4 + i;
                int hl = p >> 6, c = p & 63;
                float gsc = gb_s[gbo + c], bsc = gb_s[128 + gbo + c];
                float m = -1e30f;
                #pragma unroll
                for (int wl = 0; wl < 16; wl++)
                    m = fmaxf(m, Ds[(hl * 16 + wl) * DPAD + c] * gsc + bsc);
                atomicMax((int*)&g_rowmax[((size_t)b * Hh + h0 + hl) * Cc + N0h + c],
                          __float_as_int(m));
            }
        } else {
            const int hl = tid >> 4, wl = tid & 15;
            const size_t pix = ((size_t)b * Hh + h0 + hl) * Ww + (w0 + wl);
            const float* dr = Ds + tid * DPAD;
            if (EPI == 2) {
                #pragma unroll
                for (int c = 0; c < 64; c += 4) {
                    float4 v;
                    v.x = dr[c+0] * gb_s[gbo+c+0] + gb_s[128+gbo+c+0];
                    v.y = dr[c+1] * gb_s[gbo+c+1] + gb_s[128+gbo+c+1];
                    v.z = dr[c+2] * gb_s[gbo+c+2] + gb_s[128+gbo+c+2];
                    v.w = dr[c+3] * gb_s[gbo+c+3] + gb_s[128+gbo+c+3];
                    *(float4*)&g_c1[pix * Cc + N0h + c] = v;
                }
            } else if (EPI == 3) {
                #pragma unroll
                for (int c = 0; c < 64; c += 8) {
                    __half hv[8];
                    #pragma unroll
                    for (int u = 0; u < 8; u++) {
                        float c1v = g_c1[pix * Cc + N0h + c + u];
                        float v = dr[c+u] * gb_s[gbo+c+u] + gb_s[128+gbo+c+u] + c1v;
                        hv[u] = __float2half_rn(fmaxf(v, 0.f));
                    }
                    *(uint4*)&g_relut[pix * Cc + N0h + c] = *(const uint4*)hv;
                }
            } else {   // EPI 4: final conv, relu, NCHW output (fp32)
                const int h = h0 + hl, w = w0 + wl;
                #pragma unroll
                for (int c = 0; c < 64; c++) {
                    float v = fmaxf(dr[c] * gb_s[gbo + c] + gb_s[128 + gbo + c], 0.f);
                    outp[(((size_t)b * Cc + N0h + c) * Hh + h) * Ww + w] = v;
                }
            }
        }
        __syncthreads();   // protect Ds before next half overwrites it
    }
}

// ---------------------------------------------------------------- host
extern "C" void kernel_launch(void* const* d_in, const int* in_sizes, int n_in,
                              void* d_out, int out_size) {
    (void)in_sizes; (void)n_in; (void)out_size;
    const float* x    = (const float*)d_in[0];
    const float* w_p1 = (const float*)d_in[1];
    const float* gp1  = (const float*)d_in[2];
    const float* bp1  = (const float*)d_in[3];
    const float* w_p2 = (const float*)d_in[4];
    const float* gp2  = (const float*)d_in[5];
    const float* bp2  = (const float*)d_in[6];
    const float* w_p  = (const float*)d_in[7];
    const float* gp   = (const float*)d_in[8];
    const float* bp   = (const float*)d_in[9];
    const float* w_c1 = (const float*)d_in[10];
    const float* gc1  = (const float*)d_in[11];
    const float* bc1  = (const float*)d_in[12];
    const float* w_c2 = (const float*)d_in[13];
    const float* gc2  = (const float*)d_in[14];
    const float* bc2  = (const float*)d_in[15];
    float* out = (float*)d_out;

    zero_pools_kernel<<<(NPOOL + 255) / 256, 256>>>();
    xtrans_kernel<<<dim3(24, 96, 8), 256>>>(x);
    int twb = (NW + 255) / 256;
    wtrans_kernel<<<twb, 256>>>(w_p1, 0);
    wtrans_kernel<<<twb, 256>>>(w_p2, 1);
    wtrans_kernel<<<twb, 256>>>(w_c1, 2);
    wtrans_kernel<<<twb, 256>>>(w_p,  3);
    wtrans_kernel<<<twb, 256>>>(w_c2, 4);

    dim3 grid(Ww / 16, Hh / 8, Bn * 2);   // 6 x 12 x 16 = 1152 CTAs
    conv_mma_kernel<0><<<grid, 128>>>(0, gp1, bp1, nullptr);
    conv_mma_kernel<1><<<grid, 128>>>(1, gp2, bp2, nullptr);
    conv_mma_kernel<2><<<grid, 128>>>(2, gc1, bc1, nullptr);
    psum_kernel<<<(int)(NTEN / 8 / 256), 256>>>();   // writes psum into g_xh
    conv_mma_kernel<3><<<grid, 128>>>(3, gp,  bp,  nullptr);
    conv_mma_kernel<4><<<grid, 128>>>(4, gc2, bc2, out);
}

// round 13
// speedup vs baseline: 6.0596x; 1.0036x over previous
#include <cuda_runtime.h>
#include <cuda_pipeline.h>
#include <cuda_fp16.h>
#include <cstdint>
#include <cstddef>

// ============================================================================
// ct_layer via hand-rolled fp16 mma.sync + ldmatrix (f32 accumulate):
// 5x conv3x3(256->256)+BN as shift-GEMMs over NHWC, cp.async double buffer.
// CTA tile M=128 pixels x N=128 couts, warp tile M64xN64 (2x2 warps).
// Corner pools collapse to global row/col maxes (proven R1).
// Static smem <= 48KB, no cudaFuncSetAttribute (container-killer), no tcgen05.
// ============================================================================

constexpr int Bn = 8, Cc = 256, Hh = 96, Ww = 96;
constexpr size_t NTEN = (size_t)Bn * Hh * Ww * Cc;   // 18874368
constexpr int NW    = Cc * Cc * 9;                   // 589824
constexpr int NPOOL = Bn * 96 * Cc;                  // 196608

__device__ __align__(256) __half g_xh[NTEN];     // x NHWC fp16  ->  psum
__device__ __align__(256) __half g_relut[NTEN];  // relu(p_conv + conv1) fp16
__device__ __align__(256) float  g_c1[NTEN];     // conv_c1 out (affine) fp32
__device__ __align__(256) __half g_w2[5][NW];    // weights [k][co][ci] fp16
__device__ __align__(256) float  g_colmax[NPOOL];// [b][w][c]
__device__ __align__(256) float  g_rowmax[NPOOL];// [b][h][c]

// ---------------------------------------------------------------- prep kernels
__global__ void zero_pools_kernel() {
    int i = blockIdx.x * 256 + threadIdx.x;
    if (i < NPOOL) { g_colmax[i] = 0.f; g_rowmax[i] = 0.f; }
}

// NCHW fp32 -> NHWC fp16 (32c x 32w tiles per (b,h))
__global__ void xtrans_kernel(const float* __restrict__ x) {
    __shared__ float t[32][33];
    int b = blockIdx.z, h = blockIdx.y;
    int c0 = (blockIdx.x / 3) * 32, w0 = (blockIdx.x % 3) * 32;
    int tx = threadIdx.x & 31, ty = threadIdx.x >> 5;
    #pragma unroll
    for (int i = 0; i < 4; i++) {
        int c = ty + 8 * i;
        t[c][tx] = x[(((size_t)b * Cc + c0 + c) * Hh + h) * Ww + w0 + tx];
    }
    __syncthreads();
    #pragma unroll
    for (int i = 0; i < 4; i++) {
        int w = ty + 8 * i;
        g_xh[(((size_t)b * Hh + h) * Ww + w0 + w) * Cc + c0 + tx] =
            __float2half_rn(t[tx][w]);
    }
}

// OIHW fp32 -> [k][co][ci] fp16
__global__ void wtrans_kernel(const float* __restrict__ src, int which) {
    int idx = blockIdx.x * 256 + threadIdx.x;
    if (idx < NW) {
        int ci = idx & 255, co = (idx >> 8) & 255, k = idx >> 16;
        g_w2[which][idx] = __float2half_rn(src[((size_t)co * Cc + ci) * 9 + k]);
    }
}

// g_xh[b][h][w][c] = fp16(colmax[b][w][c] + rowmax[b][h][c])   (x is dead now)
__global__ void psum_kernel() {
    size_t e8 = ((size_t)blockIdx.x * 256 + threadIdx.x) * 8;
    int c = (int)(e8 & 255);
    size_t p = e8 >> 8;
    int w = (int)(p % 96); size_t p2 = p / 96;
    int h = (int)(p2 % 96); int b = (int)(p2 / 96);
    const float* cm = &g_colmax[((size_t)b * 96 + w) * 256 + c];
    const float* rm = &g_rowmax[((size_t)b * 96 + h) * 256 + c];
    __half hv[8];
    #pragma unroll
    for (int i = 0; i < 8; i++) hv[i] = __float2half_rn(cm[i] + rm[i]);
    *(uint4*)&g_xh[e8] = *(const uint4*)hv;
}

// ---------------------------------------------------------------- conv kernel
// K chunks of 32 channels: 9 shifts x 8 cin-chunks = 72 chunks.
constexpr int APAD = 40;                 // halves; row = 80B (LDSM conflict-free)
constexpr int A_H  = 128 * APAD;         // 5120 halves (10240 B)
constexpr int B_H  = 128 * APAD;         // 5120 halves
constexpr int STG_H = A_H + B_H;         // 10240 halves (20480 B/stage)
constexpr int DPAD = 68;                 // D half-tile: 128 x 68 fl = 34816 B
constexpr int SMRAW_B = 2 * STG_H * 2;   // 40960 B (>= D half-tile)
constexpr int NCHUNK = 72;

__device__ __forceinline__ void ldsm_x4(uint32_t r[4], const __half* p) {
    uint32_t a = (uint32_t)__cvta_generic_to_shared(p);
    asm volatile("ldmatrix.sync.aligned.m8n8.x4.shared.b16 {%0,%1,%2,%3}, [%4];"
                 : "=r"(r[0]), "=r"(r[1]), "=r"(r[2]), "=r"(r[3]) : "r"(a));
}
__device__ __forceinline__ void mma16816(float c[4], const uint32_t a[4],
                                         uint32_t b0, uint32_t b1) {
    asm volatile(
        "mma.sync.aligned.m16n8k16.row.col.f32.f16.f16.f32 "
        "{%0,%1,%2,%3}, {%4,%5,%6,%7}, {%8,%9}, {%0,%1,%2,%3};"
        : "+f"(c[0]), "+f"(c[1]), "+f"(c[2]), "+f"(c[3])
        : "r"(a[0]), "r"(a[1]), "r"(a[2]), "r"(a[3]), "r"(b0), "r"(b1));
}

// Load one K-chunk (cc = shift*8 + ch) into stage buffer s.
__device__ __forceinline__ void load_chunk(
    __half* stage, const __half* __restrict__ aSrc, const __half* __restrict__ wSrc,
    int s, int cc, int b, int h0, int w0, int N0, int tid)
{
    const int shift = cc >> 3, ch = cc & 7;
    const int dh = shift / 3 - 1, dw = (shift % 3) - 1;
    __half* As = stage + s * STG_H;
    __half* Bs = As + A_H;
    // ---- A: row = tid (pixel), 32 halves = 4 x 16B (OOB rows zero-filled) ---
    {
        const int hl = tid >> 4, wl = tid & 15;
        const int h = h0 + hl + dh, w = w0 + wl + dw;
        const bool inb = ((unsigned)h < 96u) & ((unsigned)w < 96u);
        const size_t zf = inb ? 0u : 16u;
        const __half* gp = aSrc +
            ((((size_t)b * Hh + (inb ? h : 0)) * Ww + (inb ? w : 0)) * Cc + ch * 32);
        __half* dp = As + tid * APAD;
        #pragma unroll
        for (int q = 0; q < 4; q++)
            __pipeline_memcpy_async(dp + q * 8, gp + q * 8, 16, zf);
    }
    // ---- B: 128 rows (couts) x 32 halves; thread t: row t ----
    {
        const __half* gp = wSrc + (((size_t)shift * 256 + N0 + tid) * 256 + ch * 32);
        __half* dp = Bs + tid * APAD;
        #pragma unroll
        for (int q = 0; q < 4; q++)
            __pipeline_memcpy_async(dp + q * 8, gp + q * 8, 16, 0);
    }
}

// EPI: 0 colmax, 1 rowmax, 2 store c1, 3 +c1 relu -> relut, 4 relu -> NCHW out
template <int EPI>
__global__ __launch_bounds__(128, 2) void conv_mma_kernel(
    int widx, const float* __restrict__ gg, const float* __restrict__ bb,
    float* __restrict__ outp)
{
    __shared__ __align__(16) char smraw[SMRAW_B];   // stages overlay D tile
    __shared__ float gb_s[256];
    __half* stage = (__half*)smraw;
    float*  Ds    = (float*)smraw;

    const int tid = threadIdx.x, lane = tid & 31, wid = tid >> 5;
    const int warp_m = wid >> 1, warp_n = wid & 1;     // 2x2 warp grid
    const int w0 = blockIdx.x * 16, h0 = blockIdx.y * 8;
    const int b = blockIdx.z >> 1, N0 = (blockIdx.z & 1) * 128;

    const __half* aSrc = (EPI == 4) ? g_relut : g_xh;  // EPI3 reads psum (g_xh)
    const __half* wSrc = g_w2[widx];
    gb_s[tid]       = gg[N0 + tid];
    gb_s[128 + tid] = bb[N0 + tid];

    // warp tile M64 x N64: acc[4 m-tiles][8 n-tiles][4]
    float acc[4][8][4];
    #pragma unroll
    for (int mi = 0; mi < 4; mi++)
        #pragma unroll
        for (int ni = 0; ni < 8; ni++)
            #pragma unroll
            for (int r = 0; r < 4; r++) acc[mi][ni][r] = 0.f;
    const int m0 = warp_m * 64, n0 = warp_n * 64;

    // ldmatrix lane roles: quad = lane>>3 selects matrix, lr = row within it
    const int lr = lane & 7, q2 = lane >> 3;
    const int qa_row = (q2 & 1) * 8, qa_k = (q2 >> 1) * 8;   // A: r0 mlo/klo, r1 mhi/klo, r2 mlo/khi, r3 mhi/khi
    const int qb_row = (q2 >> 1) * 8, qb_k = (q2 & 1) * 8;   // B: r0 nlo/klo, r1 nlo/khi, r2 nhi/klo, r3 nhi/khi

    load_chunk(stage, aSrc, wSrc, 0, 0, b, h0, w0, N0, tid);
    __pipeline_commit();

    for (int cc = 0; cc < NCHUNK; cc++) {
        const int s = cc & 1;
        __pipeline_wait_prior(0);     // stage s data landed
        __syncthreads();              // + everyone done computing stage s^1
        if (cc + 1 < NCHUNK) {
            load_chunk(stage, aSrc, wSrc, s ^ 1, cc + 1, b, h0, w0, N0, tid);
            __pipeline_commit();      // overlaps with compute below
        }
        const __half* As = stage + s * STG_H;
        const __half* Bs = As + A_H;
        #pragma unroll
        for (int k16 = 0; k16 < 2; k16++) {
            const int kb = k16 * 16;
            uint32_t af[4][4], bf[4][4];
            #pragma unroll
            for (int mi = 0; mi < 4; mi++)
                ldsm_x4(af[mi], As + (size_t)(m0 + mi * 16 + qa_row + lr) * APAD
                                   + kb + qa_k);
            #pragma unroll
            for (int np = 0; np < 4; np++)
                ldsm_x4(bf[np], Bs + (size_t)(n0 + np * 16 + qb_row + lr) * APAD
                                   + kb + qb_k);
            #pragma unroll
            for (int mi = 0; mi < 4; mi++)
                #pragma unroll
                for (int np = 0; np < 4; np++) {
                    mma16816(acc[mi][2 * np],     af[mi], bf[np][0], bf[np][1]);
                    mma16816(acc[mi][2 * np + 1], af[mi], bf[np][2], bf[np][3]);
                }
        }
    }
    __syncthreads();   // mainloop done; stage smem becomes the D tile

    // -------- epilogue: two passes over the N halves --------
    const int tr = lane >> 2, tc = (lane & 3) * 2;
    #pragma unroll
    for (int half = 0; half < 2; half++) {
        if (warp_n == half) {
            #pragma unroll
            for (int mi = 0; mi < 4; mi++)
                #pragma unroll
                for (int ni = 0; ni < 8; ni++) {
                    float* d0 = &Ds[(size_t)(m0 + mi * 16 + tr) * DPAD + ni * 8 + tc];
                    d0[0] = acc[mi][ni][0]; d0[1] = acc[mi][ni][1];
                    float* d1 = d0 + 8 * DPAD;
                    d1[0] = acc[mi][ni][2]; d1[1] = acc[mi][ni][3];
                }
        }
        __syncthreads();
        const int N0h = N0 + half * 64;
        const int gbo = half * 64;

        if (EPI == 0) {
            // colmax[b][w][c]: max over 8 h-rows; atomicMax vs 0-init buffer
            #pragma unroll
            for (int i = 0; i < 8; i++) {
                int p = tid * 8 + i;
                int wl = p >> 6, c = p & 63;
                float gsc = gb_s[gbo + c], bsc = gb_s[128 + gbo + c];
                float m = -1e30f;
                #pragma unroll
                for (int hl = 0; hl < 8; hl++)
                    m = fmaxf(m, Ds[(hl * 16 + wl) * DPAD + c] * gsc + bsc);
                atomicMax((int*)&g_colmax[((size_t)b * Ww + w0 + wl) * Cc + N0h + c],
                          __float_as_int(m));
            }
        } else if (EPI == 1) {
            // rowmax[b][h][c]: max over 16 w-cols
            #pragma unroll
            for (int i = 0; i < 4; i++) {
                int p = tid * 4 + i;
                int hl = p >> 6, c = p & 63;
                float gsc = gb_s[gbo + c], bsc = gb_s[128 + gbo + c];
                float m = -1e30f;
                #pragma unroll
                for (int wl = 0; wl < 16; wl++)
                    m = fmaxf(m, Ds[(hl * 16 + wl) * DPAD + c] * gsc + bsc);
                atomicMax((int*)&g_rowmax[((size_t)b * Hh + h0 + hl) * Cc + N0h + c],
                          __float_as_int(m));
            }
        } else {
            const int hl = tid >> 4, wl = tid & 15;
            const size_t pix = ((size_t)b * Hh + h0 + hl) * Ww + (w0 + wl);
            const float* dr = Ds + tid * DPAD;
            if (EPI == 2) {
                #pragma unroll
                for (int c = 0; c < 64; c += 4) {
                    float4 v;
                    v.x = dr[c+0] * gb_s[gbo+c+0] + gb_s[128+gbo+c+0];
                    v.y = dr[c+1] * gb_s[gbo+c+1] + gb_s[128+gbo+c+1];
                    v.z = dr[c+2] * gb_s[gbo+c+2] + gb_s[128+gbo+c+2];
                    v.w = dr[c+3] * gb_s[gbo+c+3] + gb_s[128+gbo+c+3];
                    *(float4*)&g_c1[pix * Cc + N0h + c] = v;
                }
            } else if (EPI == 3) {
                #pragma unroll
                for (int c = 0; c < 64; c += 8) {
                    __half hv[8];
                    #pragma unroll
                    for (int u = 0; u < 8; u++) {
                        float c1v = g_c1[pix * Cc + N0h + c + u];
                        float v = dr[c+u] * gb_s[gbo+c+u] + gb_s[128+gbo+c+u] + c1v;
                        hv[u] = __float2half_rn(fmaxf(v, 0.f));
                    }
                    *(uint4*)&g_relut[pix * Cc + N0h + c] = *(const uint4*)hv;
                }
            } else {   // EPI 4: final conv, relu, NCHW output (fp32)
                const int h = h0 + hl, w = w0 + wl;
                #pragma unroll
                for (int c = 0; c < 64; c++) {
                    float v = fmaxf(dr[c] * gb_s[gbo + c] + gb_s[128 + gbo + c], 0.f);
                    outp[(((size_t)b * Cc + N0h + c) * Hh + h) * Ww + w] = v;
                }
            }
        }
        __syncthreads();   // protect Ds before next half overwrites it
    }
}

// ---------------------------------------------------------------- host
extern "C" void kernel_launch(void* const* d_in, const int* in_sizes, int n_in,
                              void* d_out, int out_size) {
    (void)in_sizes; (void)n_in; (void)out_size;
    const float* x    = (const float*)d_in[0];
    const float* w_p1 = (const float*)d_in[1];
    const float* gp1  = (const float*)d_in[2];
    const float* bp1  = (const float*)d_in[3];
    const float* w_p2 = (const float*)d_in[4];
    const float* gp2  = (const float*)d_in[5];
    const float* bp2  = (const float*)d_in[6];
    const float* w_p  = (const float*)d_in[7];
    const float* gp   = (const float*)d_in[8];
    const float* bp   = (const float*)d_in[9];
    const float* w_c1 = (const float*)d_in[10];
    const float* gc1  = (const float*)d_in[11];
    const float* bc1  = (const float*)d_in[12];
    const float* w_c2 = (const float*)d_in[13];
    const float* gc2  = (const float*)d_in[14];
    const float* bc2  = (const float*)d_in[15];
    float* out = (float*)d_out;

    zero_pools_kernel<<<(NPOOL + 255) / 256, 256>>>();
    xtrans_kernel<<<dim3(24, 96, 8), 256>>>(x);
    int twb = (NW + 255) / 256;
    wtrans_kernel<<<twb, 256>>>(w_p1, 0);
    wtrans_kernel<<<twb, 256>>>(w_p2, 1);
    wtrans_kernel<<<twb, 256>>>(w_c1, 2);
    wtrans_kernel<<<twb, 256>>>(w_p,  3);
    wtrans_kernel<<<twb, 256>>>(w_c2, 4);

    dim3 grid(Ww / 16, Hh / 8, Bn * 2);   // 6 x 12 x 16 = 1152 CTAs
    conv_mma_kernel<0><<<grid, 128>>>(0, gp1, bp1, nullptr);
    conv_mma_kernel<1><<<grid, 128>>>(1, gp2, bp2, nullptr);
    conv_mma_kernel<2><<<grid, 128>>>(2, gc1, bc1, nullptr);
    psum_kernel<<<(int)(NTEN / 8 / 256), 256>>>();   // writes psum into g_xh
    conv_mma_kernel<3><<<grid, 128>>>(3, gp,  bp,  nullptr);
    conv_mma_kernel<4><<<grid, 128>>>(4, gc2, bc2, out);
}

// round 16
// speedup vs baseline: 6.8319x; 1.1275x over previous
#include <cuda_runtime.h>
#include <cuda_pipeline.h>
#include <cuda_fp16.h>
#include <cstdint>
#include <cstddef>

// ============================================================================
// ct_layer via hand-rolled fp16 mma.sync + ldmatrix (f32 accumulate):
// 5x conv3x3(256->256)+BN as shift-GEMMs over NHWC.
// 3-stage cp.async pipeline, K=16 chunks (144 = 9 shifts x 16 cin-chunks).
// CTA tile M=128 pixels x N=128 couts, warp tile M64xN64 (2x2 warps).
// Corner pools collapse to global row/col maxes (proven R1).
// Static smem <= 48KB, no cudaFuncSetAttribute, no tcgen05 (toolchain-safe).
// R15 fix: compute-stage index is cc%3 (tracked via scur), NOT derived from
// the post-increment snext (R14's off-by-one read the wrong stage -> inf).
// ============================================================================

constexpr int Bn = 8, Cc = 256, Hh = 96, Ww = 96;
constexpr size_t NTEN = (size_t)Bn * Hh * Ww * Cc;   // 18874368
constexpr int NW    = Cc * Cc * 9;                   // 589824
constexpr int NPOOL = Bn * 96 * Cc;                  // 196608

__device__ __align__(256) __half g_xh[NTEN];     // x NHWC fp16  ->  psum
__device__ __align__(256) __half g_relut[NTEN];  // relu(p_conv + conv1) fp16
__device__ __align__(256) float  g_c1[NTEN];     // conv_c1 out (affine) fp32
__device__ __align__(256) __half g_w2[5][NW];    // weights [k][co][ci] fp16
__device__ __align__(256) float  g_colmax[NPOOL];// [b][w][c]
__device__ __align__(256) float  g_rowmax[NPOOL];// [b][h][c]

// ---------------------------------------------------------------- prep kernels
__global__ void zero_pools_kernel() {
    int i = blockIdx.x * 256 + threadIdx.x;
    if (i < NPOOL) { g_colmax[i] = 0.f; g_rowmax[i] = 0.f; }
}

// NCHW fp32 -> NHWC fp16 (32c x 32w tiles per (b,h))
__global__ void xtrans_kernel(const float* __restrict__ x) {
    __shared__ float t[32][33];
    int b = blockIdx.z, h = blockIdx.y;
    int c0 = (blockIdx.x / 3) * 32, w0 = (blockIdx.x % 3) * 32;
    int tx = threadIdx.x & 31, ty = threadIdx.x >> 5;
    #pragma unroll
    for (int i = 0; i < 4; i++) {
        int c = ty + 8 * i;
        t[c][tx] = x[(((size_t)b * Cc + c0 + c) * Hh + h) * Ww + w0 + tx];
    }
    __syncthreads();
    #pragma unroll
    for (int i = 0; i < 4; i++) {
        int w = ty + 8 * i;
        g_xh[(((size_t)b * Hh + h) * Ww + w0 + w) * Cc + c0 + tx] =
            __float2half_rn(t[tx][w]);
    }
}

// OIHW fp32 -> [k][co][ci] fp16
__global__ void wtrans_kernel(const float* __restrict__ src, int which) {
    int idx = blockIdx.x * 256 + threadIdx.x;
    if (idx < NW) {
        int ci = idx & 255, co = (idx >> 8) & 255, k = idx >> 16;
        g_w2[which][idx] = __float2half_rn(src[((size_t)co * Cc + ci) * 9 + k]);
    }
}

// g_xh[b][h][w][c] = fp16(colmax[b][w][c] + rowmax[b][h][c])   (x is dead now)
__global__ void psum_kernel() {
    size_t e8 = ((size_t)blockIdx.x * 256 + threadIdx.x) * 8;
    int c = (int)(e8 & 255);
    size_t p = e8 >> 8;
    int w = (int)(p % 96); size_t p2 = p / 96;
    int h = (int)(p2 % 96); int b = (int)(p2 / 96);
    const float* cm = &g_colmax[((size_t)b * 96 + w) * 256 + c];
    const float* rm = &g_rowmax[((size_t)b * 96 + h) * 256 + c];
    __half hv[8];
    #pragma unroll
    for (int i = 0; i < 8; i++) hv[i] = __float2half_rn(cm[i] + rm[i]);
    *(uint4*)&g_xh[e8] = *(const uint4*)hv;
}

// ---------------------------------------------------------------- conv kernel
// K chunks of 16 channels: 9 shifts x 16 cin-chunks = 144 chunks, 3 stages.
constexpr int APAD = 24;                 // halves; row = 48B (LDSM conflict-free)
constexpr int A_H  = 128 * APAD;         // 3072 halves (6144 B)
constexpr int B_H  = 128 * APAD;         // 3072 halves
constexpr int STG_H = A_H + B_H;         // 6144 halves (12288 B/stage)
constexpr int NSTAGE = 3;
constexpr int DPAD = 68;                 // D half-tile: 128 x 68 fl = 34816 B
constexpr int SMRAW_B = NSTAGE * STG_H * 2;  // 36864 B (>= D half-tile)
constexpr int NCHUNK = 144;

__device__ __forceinline__ void ldsm_x4(uint32_t r[4], const __half* p) {
    uint32_t a = (uint32_t)__cvta_generic_to_shared(p);
    asm volatile("ldmatrix.sync.aligned.m8n8.x4.shared.b16 {%0,%1,%2,%3}, [%4];"
                 : "=r"(r[0]), "=r"(r[1]), "=r"(r[2]), "=r"(r[3]) : "r"(a));
}
__device__ __forceinline__ void mma16816(float c[4], const uint32_t a[4],
                                         uint32_t b0, uint32_t b1) {
    asm volatile(
        "mma.sync.aligned.m16n8k16.row.col.f32.f16.f16.f32 "
        "{%0,%1,%2,%3}, {%4,%5,%6,%7}, {%8,%9}, {%0,%1,%2,%3};"
        : "+f"(c[0]), "+f"(c[1]), "+f"(c[2]), "+f"(c[3])
        : "r"(a[0]), "r"(a[1]), "r"(a[2]), "r"(a[3]), "r"(b0), "r"(b1));
}

// Load one K-chunk (cc = shift*16 + ch, 16 channels) into stage buffer s.
__device__ __forceinline__ void load_chunk(
    __half* stage, const __half* __restrict__ aSrc, const __half* __restrict__ wSrc,
    int s, int cc, int b, int h0, int w0, int N0, int tid)
{
    const int shift = cc >> 4, ch = cc & 15;
    const int dh = shift / 3 - 1, dw = (shift % 3) - 1;
    __half* As = stage + s * STG_H;
    __half* Bs = As + A_H;
    // ---- A: row = tid (pixel), 16 halves = 2 x 16B (OOB rows zero-filled) ---
    {
        const int hl = tid >> 4, wl = tid & 15;
        const int h = h0 + hl + dh, w = w0 + wl + dw;
        const bool inb = ((unsigned)h < 96u) & ((unsigned)w < 96u);
        const size_t zf = inb ? 0u : 16u;
        const __half* gp = aSrc +
            ((((size_t)b * Hh + (inb ? h : 0)) * Ww + (inb ? w : 0)) * Cc + ch * 16);
        __half* dp = As + tid * APAD;
        __pipeline_memcpy_async(dp,     gp,     16, zf);
        __pipeline_memcpy_async(dp + 8, gp + 8, 16, zf);
    }
    // ---- B: 128 rows (couts) x 16 halves; thread t: row t ----
    {
        const __half* gp = wSrc + (((size_t)shift * 256 + N0 + tid) * 256 + ch * 16);
        __half* dp = Bs + tid * APAD;
        __pipeline_memcpy_async(dp,     gp,     16, 0);
        __pipeline_memcpy_async(dp + 8, gp + 8, 16, 0);
    }
}

// EPI: 0 colmax, 1 rowmax, 2 store c1, 3 +c1 relu -> relut, 4 relu -> NCHW out
template <int EPI>
__global__ __launch_bounds__(128, 2) void conv_mma_kernel(
    int widx, const float* __restrict__ gg, const float* __restrict__ bb,
    float* __restrict__ outp)
{
    __shared__ __align__(16) char smraw[SMRAW_B];   // stages overlay D tile
    __shared__ float gb_s[256];
    __half* stage = (__half*)smraw;
    float*  Ds    = (float*)smraw;

    const int tid = threadIdx.x, lane = tid & 31, wid = tid >> 5;
    const int warp_m = wid >> 1, warp_n = wid & 1;     // 2x2 warp grid
    const int w0 = blockIdx.x * 16, h0 = blockIdx.y * 8;
    const int b = blockIdx.z >> 1, N0 = (blockIdx.z & 1) * 128;

    const __half* aSrc = (EPI == 4) ? g_relut : g_xh;  // EPI3 reads psum (g_xh)
    const __half* wSrc = g_w2[widx];
    gb_s[tid]       = gg[N0 + tid];
    gb_s[128 + tid] = bb[N0 + tid];

    // warp tile M64 x N64: acc[4 m-tiles][8 n-tiles][4]
    float acc[4][8][4];
    #pragma unroll
    for (int mi = 0; mi < 4; mi++)
        #pragma unroll
        for (int ni = 0; ni < 8; ni++)
            #pragma unroll
            for (int r = 0; r < 4; r++) acc[mi][ni][r] = 0.f;
    const int m0 = warp_m * 64, n0 = warp_n * 64;

    // ldmatrix lane roles
    const int lr = lane & 7, q2 = lane >> 3;
    const int qa_row = (q2 & 1) * 8, qa_k = (q2 >> 1) * 8;
    const int qb_row = (q2 >> 1) * 8, qb_k = (q2 & 1) * 8;

    // prologue: chunks 0,1 into stages 0,1
    load_chunk(stage, aSrc, wSrc, 0, 0, b, h0, w0, N0, tid);
    __pipeline_commit();
    load_chunk(stage, aSrc, wSrc, 1, 1, b, h0, w0, N0, tid);
    __pipeline_commit();

    int snext = 2;   // stage receiving chunk cc+2
    int scur  = 0;   // stage holding chunk cc  (== cc % 3)
    for (int cc = 0; cc < NCHUNK; cc++) {
        __pipeline_wait_prior(1);     // chunk cc's copies landed (this thread)
        __syncthreads();              // visibility + all done with stage snext
        if (cc + 2 < NCHUNK)
            load_chunk(stage, aSrc, wSrc, snext, cc + 2, b, h0, w0, N0, tid);
        __pipeline_commit();          // always commit: exact group accounting

        const __half* As = stage + scur * STG_H;
        const __half* Bs = As + A_H;
        uint32_t af[4][4], bf[4][4];
        #pragma unroll
        for (int mi = 0; mi < 4; mi++)
            ldsm_x4(af[mi], As + (size_t)(m0 + mi * 16 + qa_row + lr) * APAD + qa_k);
        #pragma unroll
        for (int np = 0; np < 4; np++)
            ldsm_x4(bf[np], Bs + (size_t)(n0 + np * 16 + qb_row + lr) * APAD + qb_k);
        #pragma unroll
        for (int mi = 0; mi < 4; mi++)
            #pragma unroll
            for (int np = 0; np < 4; np++) {
                mma16816(acc[mi][2 * np],     af[mi], bf[np][0], bf[np][1]);
                mma16816(acc[mi][2 * np + 1], af[mi], bf[np][2], bf[np][3]);
            }

        snext = (snext == 2) ? 0 : snext + 1;
        scur  = (scur  == 2) ? 0 : scur  + 1;
    }
    __syncthreads();   // mainloop done; stage smem becomes the D tile

    // -------- epilogue: two passes over the N halves --------
    const int tr = lane >> 2, tc = (lane & 3) * 2;
    #pragma unroll
    for (int half = 0; half < 2; half++) {
        if (warp_n == half) {
            #pragma unroll
            for (int mi = 0; mi < 4; mi++)
                #pragma unroll
                for (int ni = 0; ni < 8; ni++) {
                    float* d0 = &Ds[(size_t)(m0 + mi * 16 + tr) * DPAD + ni * 8 + tc];
                    d0[0] = acc[mi][ni][0]; d0[1] = acc[mi][ni][1];
                    float* d1 = d0 + 8 * DPAD;
                    d1[0] = acc[mi][ni][2]; d1[1] = acc[mi][ni][3];
                }
        }
        __syncthreads();
        const int N0h = N0 + half * 64;
        const int gbo = half * 64;

        if (EPI == 0) {
            // colmax[b][w][c]: max over 8 h-rows; atomicMax vs 0-init buffer
            #pragma unroll
            for (int i = 0; i < 8; i++) {
                int p = tid * 8 + i;
                int wl = p >> 6, c = p & 63;
                float gsc = gb_s[gbo + c], bsc = gb_s[128 + gbo + c];
                float m = -1e30f;
                #pragma unroll
                for (int hl = 0; hl < 8; hl++)
                    m = fmaxf(m, Ds[(hl * 16 + wl) * DPAD + c] * gsc + bsc);
                atomicMax((int*)&g_colmax[((size_t)b * Ww + w0 + wl) * Cc + N0h + c],
                          __float_as_int(m));
            }
        } else if (EPI == 1) {
            // rowmax[b][h][c]: max over 16 w-cols
            #pragma unroll
            for (int i = 0; i < 4; i++) {
                int p = tid * 4 + i;
                int hl = p >> 6, c = p & 63;
                float gsc = gb_s[gbo + c], bsc = gb_s[128 + gbo + c];
                float m = -1e30f;
                #pragma unroll
                for (int wl = 0; wl < 16; wl++)
                    m = fmaxf(m, Ds[(hl * 16 + wl) * DPAD + c] * gsc + bsc);
                atomicMax((int*)&g_rowmax[((size_t)b * Hh + h0 + hl) * Cc + N0h + c],
                          __float_as_int(m));
            }
        } else {
            const int hl = tid >> 4, wl = tid & 15;
            const size_t pix = ((size_t)b * Hh + h0 + hl) * Ww + (w0 + wl);
            const float* dr = Ds + tid * DPAD;
            if (EPI == 2) {
                #pragma unroll
                for (int c = 0; c < 64; c += 4) {
                    float4 v;
                    v.x = dr[c+0] * gb_s[gbo+c+0] + gb_s[128+gbo+c+0];
                    v.y = dr[c+1] * gb_s[gbo+c+1] + gb_s[128+gbo+c+1];
                    v.z = dr[c+2] * gb_s[gbo+c+2] + gb_s[128+gbo+c+2];
                    v.w = dr[c+3] * gb_s[gbo+c+3] + gb_s[128+gbo+c+3];
                    *(float4*)&g_c1[pix * Cc + N0h + c] = v;
                }
            } else if (EPI == 3) {
                #pragma unroll
                for (int c = 0; c < 64; c += 8) {
                    __half hv[8];
                    #pragma unroll
                    for (int u = 0; u < 8; u++) {
                        float c1v = g_c1[pix * Cc + N0h + c + u];
                        float v = dr[c+u] * gb_s[gbo+c+u] + gb_s[128+gbo+c+u] + c1v;
                        hv[u] = __float2half_rn(fmaxf(v, 0.f));
                    }
                    *(uint4*)&g_relut[pix * Cc + N0h + c] = *(const uint4*)hv;
                }
            } else {   // EPI 4: final conv, relu, NCHW output (fp32)
                const int h = h0 + hl, w = w0 + wl;
                #pragma unroll
                for (int c = 0; c < 64; c++) {
                    float v = fmaxf(dr[c] * gb_s[gbo + c] + gb_s[128 + gbo + c], 0.f);
                    outp[(((size_t)b * Cc + N0h + c) * Hh + h) * Ww + w] = v;
                }
            }
        }
        __syncthreads();   // protect Ds before next half overwrites it
    }
}

// ---------------------------------------------------------------- host
extern "C" void kernel_launch(void* const* d_in, const int* in_sizes, int n_in,
                              void* d_out, int out_size) {
    (void)in_sizes; (void)n_in; (void)out_size;
    const float* x    = (const float*)d_in[0];
    const float* w_p1 = (const float*)d_in[1];
    const float* gp1  = (const float*)d_in[2];
    const float* bp1  = (const float*)d_in[3];
    const float* w_p2 = (const float*)d_in[4];
    const float* gp2  = (const float*)d_in[5];
    const float* bp2  = (const float*)d_in[6];
    const float* w_p  = (const float*)d_in[7];
    const float* gp   = (const float*)d_in[8];
    const float* bp   = (const float*)d_in[9];
    const float* w_c1 = (const float*)d_in[10];
    const float* gc1  = (const float*)d_in[11];
    const float* bc1  = (const float*)d_in[12];
    const float* w_c2 = (const float*)d_in[13];
    const float* gc2  = (const float*)d_in[14];
    const float* bc2  = (const float*)d_in[15];
    float* out = (float*)d_out;

    zero_pools_kernel<<<(NPOOL + 255) / 256, 256>>>();
    xtrans_kernel<<<dim3(24, 96, 8), 256>>>(x);
    int twb = (NW + 255) / 256;
    wtrans_kernel<<<twb, 256>>>(w_p1, 0);
    wtrans_kernel<<<twb, 256>>>(w_p2, 1);
    wtrans_kernel<<<twb, 256>>>(w_c1, 2);
    wtrans_kernel<<<twb, 256>>>(w_p,  3);
    wtrans_kernel<<<twb, 256>>>(w_c2, 4);

    dim3 grid(Ww / 16, Hh / 8, Bn * 2);   // 6 x 12 x 16 = 1152 CTAs
    conv_mma_kernel<0><<<grid, 128>>>(0, gp1, bp1, nullptr);
    conv_mma_kernel<1><<<grid, 128>>>(1, gp2, bp2, nullptr);
    conv_mma_kernel<2><<<grid, 128>>>(2, gc1, bc1, nullptr);
    psum_kernel<<<(int)(NTEN / 8 / 256), 256>>>();   // writes psum into g_xh
    conv_mma_kernel<3><<<grid, 128>>>(3, gp,  bp,  nullptr);
    conv_mma_kernel<4><<<grid, 128>>>(4, gc2, bc2, out);
}

// round 17
// speedup vs baseline: 7.6539x; 1.1203x over previous
#include <cuda_runtime.h>
#include <cuda_pipeline.h>
#include <cuda_fp16.h>
#include <cstdint>
#include <cstddef>

// ============================================================================
// ct_layer via hand-rolled fp16 mma.sync + ldmatrix (f32 accumulate):
// 5x conv3x3(256->256)+BN as shift-GEMMs over NHWC.
// 3-stage cp.async pipeline, K=16 chunks (144 = 9 shifts x 16 cin-chunks).
// CTA: 256 threads, tile M=128 x N=128; warp tile M64xN32 (2x4 warp grid)
//   -> 16 warps/SM at occ 2 for latency hiding (R16 was 8 warps/SM).
// Corner pools collapse to global row/col maxes (proven R1).
// Static smem <= 48KB, no cudaFuncSetAttribute, no tcgen05 (toolchain-safe).
// ============================================================================

constexpr int Bn = 8, Cc = 256, Hh = 96, Ww = 96;
constexpr size_t NTEN = (size_t)Bn * Hh * Ww * Cc;   // 18874368
constexpr int NW    = Cc * Cc * 9;                   // 589824
constexpr int NPOOL = Bn * 96 * Cc;                  // 196608

__device__ __align__(256) __half g_xh[NTEN];     // x NHWC fp16  ->  psum
__device__ __align__(256) __half g_relut[NTEN];  // relu(p_conv + conv1) fp16
__device__ __align__(256) float  g_c1[NTEN];     // conv_c1 out (affine) fp32
__device__ __align__(256) __half g_w2[5][NW];    // weights [k][co][ci] fp16
__device__ __align__(256) float  g_colmax[NPOOL];// [b][w][c]
__device__ __align__(256) float  g_rowmax[NPOOL];// [b][h][c]

// ---------------------------------------------------------------- prep kernels
__global__ void zero_pools_kernel() {
    int i = blockIdx.x * 256 + threadIdx.x;
    if (i < NPOOL) { g_colmax[i] = 0.f; g_rowmax[i] = 0.f; }
}

// NCHW fp32 -> NHWC fp16 (32c x 32w tiles per (b,h))
__global__ void xtrans_kernel(const float* __restrict__ x) {
    __shared__ float t[32][33];
    int b = blockIdx.z, h = blockIdx.y;
    int c0 = (blockIdx.x / 3) * 32, w0 = (blockIdx.x % 3) * 32;
    int tx = threadIdx.x & 31, ty = threadIdx.x >> 5;
    #pragma unroll
    for (int i = 0; i < 4; i++) {
        int c = ty + 8 * i;
        t[c][tx] = x[(((size_t)b * Cc + c0 + c) * Hh + h) * Ww + w0 + tx];
    }
    __syncthreads();
    #pragma unroll
    for (int i = 0; i < 4; i++) {
        int w = ty + 8 * i;
        g_xh[(((size_t)b * Hh + h) * Ww + w0 + w) * Cc + c0 + tx] =
            __float2half_rn(t[tx][w]);
    }
}

// OIHW fp32 -> [k][co][ci] fp16
__global__ void wtrans_kernel(const float* __restrict__ src, int which) {
    int idx = blockIdx.x * 256 + threadIdx.x;
    if (idx < NW) {
        int ci = idx & 255, co = (idx >> 8) & 255, k = idx >> 16;
        g_w2[which][idx] = __float2half_rn(src[((size_t)co * Cc + ci) * 9 + k]);
    }
}

// g_xh[b][h][w][c] = fp16(colmax[b][w][c] + rowmax[b][h][c])   (x is dead now)
__global__ void psum_kernel() {
    size_t e8 = ((size_t)blockIdx.x * 256 + threadIdx.x) * 8;
    int c = (int)(e8 & 255);
    size_t p = e8 >> 8;
    int w = (int)(p % 96); size_t p2 = p / 96;
    int h = (int)(p2 % 96); int b = (int)(p2 / 96);
    const float* cm = &g_colmax[((size_t)b * 96 + w) * 256 + c];
    const float* rm = &g_rowmax[((size_t)b * 96 + h) * 256 + c];
    __half hv[8];
    #pragma unroll
    for (int i = 0; i < 8; i++) hv[i] = __float2half_rn(cm[i] + rm[i]);
    *(uint4*)&g_xh[e8] = *(const uint4*)hv;
}

// ---------------------------------------------------------------- conv kernel
// K chunks of 16 channels: 9 shifts x 16 cin-chunks = 144 chunks, 3 stages.
constexpr int APAD = 24;                 // halves; row = 48B (LDSM conflict-free)
constexpr int A_H  = 128 * APAD;         // 3072 halves (6144 B)
constexpr int B_H  = 128 * APAD;         // 3072 halves
constexpr int STG_H = A_H + B_H;         // 6144 halves (12288 B/stage)
constexpr int NSTAGE = 3;
constexpr int DPAD = 68;                 // D half-tile: 128 x 68 fl = 34816 B
constexpr int SMRAW_B = NSTAGE * STG_H * 2;  // 36864 B (>= D half-tile)
constexpr int NCHUNK = 144;

__device__ __forceinline__ void ldsm_x4(uint32_t r[4], const __half* p) {
    uint32_t a = (uint32_t)__cvta_generic_to_shared(p);
    asm volatile("ldmatrix.sync.aligned.m8n8.x4.shared.b16 {%0,%1,%2,%3}, [%4];"
                 : "=r"(r[0]), "=r"(r[1]), "=r"(r[2]), "=r"(r[3]) : "r"(a));
}
__device__ __forceinline__ void mma16816(float c[4], const uint32_t a[4],
                                         uint32_t b0, uint32_t b1) {
    asm volatile(
        "mma.sync.aligned.m16n8k16.row.col.f32.f16.f16.f32 "
        "{%0,%1,%2,%3}, {%4,%5,%6,%7}, {%8,%9}, {%0,%1,%2,%3};"
        : "+f"(c[0]), "+f"(c[1]), "+f"(c[2]), "+f"(c[3])
        : "r"(a[0]), "r"(a[1]), "r"(a[2]), "r"(a[3]), "r"(b0), "r"(b1));
}

// Load one K-chunk (cc = shift*16 + ch, 16 channels) into stage buffer s.
// 256 threads: thread t handles row t>>1 (A pixel / B cout), 8-ch half t&1.
__device__ __forceinline__ void load_chunk(
    __half* stage, const __half* __restrict__ aSrc, const __half* __restrict__ wSrc,
    int s, int cc, int b, int h0, int w0, int N0, int tid)
{
    const int shift = cc >> 4, ch = cc & 15;
    const int dh = shift / 3 - 1, dw = (shift % 3) - 1;
    __half* As = stage + s * STG_H;
    __half* Bs = As + A_H;
    const int row = tid >> 1, half = tid & 1;
    // ---- A: pixel row, 8 halves = 1 x 16B (OOB rows zero-filled) ----
    {
        const int hl = row >> 4, wl = row & 15;
        const int h = h0 + hl + dh, w = w0 + wl + dw;
        const bool inb = ((unsigned)h < 96u) & ((unsigned)w < 96u);
        const size_t zf = inb ? 0u : 16u;
        const __half* gp = aSrc +
            ((((size_t)b * Hh + (inb ? h : 0)) * Ww + (inb ? w : 0)) * Cc
             + ch * 16 + half * 8);
        __pipeline_memcpy_async(As + row * APAD + half * 8, gp, 16, zf);
    }
    // ---- B: cout row ----
    {
        const __half* gp = wSrc +
            (((size_t)shift * 256 + N0 + row) * 256 + ch * 16 + half * 8);
        __pipeline_memcpy_async(Bs + row * APAD + half * 8, gp, 16, 0);
    }
}

// EPI: 0 colmax, 1 rowmax, 2 store c1, 3 +c1 relu -> relut, 4 relu -> NCHW out
template <int EPI>
__global__ __launch_bounds__(256, 2) void conv_mma_kernel(
    int widx, const float* __restrict__ gg, const float* __restrict__ bb,
    float* __restrict__ outp)
{
    __shared__ __align__(16) char smraw[SMRAW_B];   // stages overlay D tile
    __shared__ float gb_s[256];
    __half* stage = (__half*)smraw;
    float*  Ds    = (float*)smraw;

    const int tid = threadIdx.x, lane = tid & 31, wid = tid >> 5;
    const int warp_m = wid >> 2, warp_n = wid & 3;     // 2x4 warp grid
    const int w0 = blockIdx.x * 16, h0 = blockIdx.y * 8;
    const int b = blockIdx.z >> 1, N0 = (blockIdx.z & 1) * 128;

    const __half* aSrc = (EPI == 4) ? g_relut : g_xh;  // EPI3 reads psum (g_xh)
    const __half* wSrc = g_w2[widx];
    gb_s[tid] = (tid < 128) ? gg[N0 + tid] : bb[N0 + tid - 128];

    // warp tile M64 x N32: acc[4 m-tiles][4 n8-tiles][4]
    float acc[4][4][4];
    #pragma unroll
    for (int mi = 0; mi < 4; mi++)
        #pragma unroll
        for (int ni = 0; ni < 4; ni++)
            #pragma unroll
            for (int r = 0; r < 4; r++) acc[mi][ni][r] = 0.f;
    const int m0 = warp_m * 64, n0 = warp_n * 32;

    // ldmatrix lane roles
    const int lr = lane & 7, q2 = lane >> 3;
    const int qa_row = (q2 & 1) * 8, qa_k = (q2 >> 1) * 8;
    const int qb_row = (q2 >> 1) * 8, qb_k = (q2 & 1) * 8;

    // prologue: chunks 0,1 into stages 0,1
    load_chunk(stage, aSrc, wSrc, 0, 0, b, h0, w0, N0, tid);
    __pipeline_commit();
    load_chunk(stage, aSrc, wSrc, 1, 1, b, h0, w0, N0, tid);
    __pipeline_commit();

    int snext = 2;   // stage receiving chunk cc+2
    int scur  = 0;   // stage holding chunk cc  (== cc % 3)
    for (int cc = 0; cc < NCHUNK; cc++) {
        __pipeline_wait_prior(1);     // chunk cc's copies landed (this thread)
        __syncthreads();              // visibility + all done with stage snext
        if (cc + 2 < NCHUNK)
            load_chunk(stage, aSrc, wSrc, snext, cc + 2, b, h0, w0, N0, tid);
        __pipeline_commit();          // always commit: exact group accounting

        const __half* As = stage + scur * STG_H;
        const __half* Bs = As + A_H;
        uint32_t af[4][4], bf[2][4];
        #pragma unroll
        for (int mi = 0; mi < 4; mi++)
            ldsm_x4(af[mi], As + (size_t)(m0 + mi * 16 + qa_row + lr) * APAD + qa_k);
        #pragma unroll
        for (int np = 0; np < 2; np++)
            ldsm_x4(bf[np], Bs + (size_t)(n0 + np * 16 + qb_row + lr) * APAD + qb_k);
        #pragma unroll
        for (int mi = 0; mi < 4; mi++)
            #pragma unroll
            for (int np = 0; np < 2; np++) {
                mma16816(acc[mi][2 * np],     af[mi], bf[np][0], bf[np][1]);
                mma16816(acc[mi][2 * np + 1], af[mi], bf[np][2], bf[np][3]);
            }

        snext = (snext == 2) ? 0 : snext + 1;
        scur  = (scur  == 2) ? 0 : scur  + 1;
    }
    __syncthreads();   // mainloop done; stage smem becomes the D tile

    // -------- epilogue: two passes over the N halves --------
    const int tr = lane >> 2, tc = (lane & 3) * 2;
    #pragma unroll
    for (int half = 0; half < 2; half++) {
        if ((warp_n >> 1) == half) {
            const int ncol = (warp_n & 1) * 32;
            #pragma unroll
            for (int mi = 0; mi < 4; mi++)
                #pragma unroll
                for (int ni = 0; ni < 4; ni++) {
                    float* d0 = &Ds[(size_t)(m0 + mi * 16 + tr) * DPAD
                                    + ncol + ni * 8 + tc];
                    d0[0] = acc[mi][ni][0]; d0[1] = acc[mi][ni][1];
                    float* d1 = d0 + 8 * DPAD;
                    d1[0] = acc[mi][ni][2]; d1[1] = acc[mi][ni][3];
                }
        }
        __syncthreads();
        const int N0h = N0 + half * 64;
        const int gbo = half * 64;

        if (EPI == 0) {
            // colmax[b][w][c]: 1024 outputs (16w x 64c), max over 8 h-rows
            #pragma unroll
            for (int i = 0; i < 4; i++) {
                int p = tid * 4 + i;
                int wl = p >> 6, c = p & 63;
                float gsc = gb_s[gbo + c], bsc = gb_s[128 + gbo + c];
                float m = -1e30f;
                #pragma unroll
                for (int hl = 0; hl < 8; hl++)
                    m = fmaxf(m, Ds[(hl * 16 + wl) * DPAD + c] * gsc + bsc);
                atomicMax((int*)&g_colmax[((size_t)b * Ww + w0 + wl) * Cc + N0h + c],
                          __float_as_int(m));
            }
        } else if (EPI == 1) {
            // rowmax[b][h][c]: 512 outputs (8h x 64c), max over 16 w-cols
            #pragma unroll
            for (int i = 0; i < 2; i++) {
                int p = tid * 2 + i;
                int hl = p >> 6, c = p & 63;
                float gsc = gb_s[gbo + c], bsc = gb_s[128 + gbo + c];
                float m = -1e30f;
                #pragma unroll
                for (int wl = 0; wl < 16; wl++)
                    m = fmaxf(m, Ds[(hl * 16 + wl) * DPAD + c] * gsc + bsc);
                atomicMax((int*)&g_rowmax[((size_t)b * Hh + h0 + hl) * Cc + N0h + c],
                          __float_as_int(m));
            }
        } else {
            // thread handles pixel tid>>1, 32-channel half (tid&1)
            const int prow = tid >> 1, chb = (tid & 1) * 32;
            const int hl = prow >> 4, wl = prow & 15;
            const size_t pix = ((size_t)b * Hh + h0 + hl) * Ww + (w0 + wl);
            const float* dr = Ds + prow * DPAD + chb;
            if (EPI == 2) {
                #pragma unroll
                for (int c = 0; c < 32; c += 4) {
                    float4 v;
                    v.x = dr[c+0] * gb_s[gbo+chb+c+0] + gb_s[128+gbo+chb+c+0];
                    v.y = dr[c+1] * gb_s[gbo+chb+c+1] + gb_s[128+gbo+chb+c+1];
                    v.z = dr[c+2] * gb_s[gbo+chb+c+2] + gb_s[128+gbo+chb+c+2];
                    v.w = dr[c+3] * gb_s[gbo+chb+c+3] + gb_s[128+gbo+chb+c+3];
                    *(float4*)&g_c1[pix * Cc + N0h + chb + c] = v;
                }
            } else if (EPI == 3) {
                #pragma unroll
                for (int c = 0; c < 32; c += 8) {
                    __half hv[8];
                    #pragma unroll
                    for (int u = 0; u < 8; u++) {
                        float c1v = g_c1[pix * Cc + N0h + chb + c + u];
                        float v = dr[c+u] * gb_s[gbo+chb+c+u]
                                  + gb_s[128+gbo+chb+c+u] + c1v;
                        hv[u] = __float2half_rn(fmaxf(v, 0.f));
                    }
                    *(uint4*)&g_relut[pix * Cc + N0h + chb + c] = *(const uint4*)hv;
                }
            } else {   // EPI 4: final conv, relu, NCHW output (fp32)
                const int h = h0 + hl, w = w0 + wl;
                #pragma unroll
                for (int c = 0; c < 32; c++) {
                    float v = fmaxf(dr[c] * gb_s[gbo + chb + c]
                                    + gb_s[128 + gbo + chb + c], 0.f);
                    outp[(((size_t)b * Cc + N0h + chb + c) * Hh + h) * Ww + w] = v;
                }
            }
        }
        __syncthreads();   // protect Ds before next half overwrites it
    }
}

// ---------------------------------------------------------------- host
extern "C" void kernel_launch(void* const* d_in, const int* in_sizes, int n_in,
                              void* d_out, int out_size) {
    (void)in_sizes; (void)n_in; (void)out_size;
    const float* x    = (const float*)d_in[0];
    const float* w_p1 = (const float*)d_in[1];
    const float* gp1  = (const float*)d_in[2];
    const float* bp1  = (const float*)d_in[3];
    const float* w_p2 = (const float*)d_in[4];
    const float* gp2  = (const float*)d_in[5];
    const float* bp2  = (const float*)d_in[6];
    const float* w_p  = (const float*)d_in[7];
    const float* gp   = (const float*)d_in[8];
    const float* bp   = (const float*)d_in[9];
    const float* w_c1 = (const float*)d_in[10];
    const float* gc1  = (const float*)d_in[11];
    const float* bc1  = (const float*)d_in[12];
    const float* w_c2 = (const float*)d_in[13];
    const float* gc2  = (const float*)d_in[14];
    const float* bc2  = (const float*)d_in[15];
    float* out = (float*)d_out;

    zero_pools_kernel<<<(NPOOL + 255) / 256, 256>>>();
    xtrans_kernel<<<dim3(24, 96, 8), 256>>>(x);
    int twb = (NW + 255) / 256;
    wtrans_kernel<<<twb, 256>>>(w_p1, 0);
    wtrans_kernel<<<twb, 256>>>(w_p2, 1);
    wtrans_kernel<<<twb, 256>>>(w_c1, 2);
    wtrans_kernel<<<twb, 256>>>(w_p,  3);
    wtrans_kernel<<<twb, 256>>>(w_c2, 4);

    dim3 grid(Ww / 16, Hh / 8, Bn * 2);   // 6 x 12 x 16 = 1152 CTAs
    conv_mma_kernel<0><<<grid, 256>>>(0, gp1, bp1, nullptr);
    conv_mma_kernel<1><<<grid, 256>>>(1, gp2, bp2, nullptr);
    conv_mma_kernel<2><<<grid, 256>>>(2, gc1, bc1, nullptr);
    psum_kernel<<<(int)(NTEN / 8 / 256), 256>>>();   // writes psum into g_xh
    conv_mma_kernel<3><<<grid, 256>>>(3, gp,  bp,  nullptr);
    conv_mma_kernel<4><<<grid, 256>>>(4, gc2, bc2, out);
}